// round 7
// baseline (speedup 1.0000x reference)
#include <cuda_runtime.h>
#include <cuda_bf16.h>
#include <math.h>

#define BATCH 16
#define CCH   384
#define HN    3136
#define NPAD  3200          // HN padded to multiple of 128
#define TC    1152

// ---------------- scratch (device globals, zero-initialized) ----------------
__device__ __nv_bfloat16 g_xT   [(size_t)BATCH * NPAD * CCH];  // BN(x)^T [b][n][c]
__device__ __nv_bfloat16 g_qkvb [(size_t)BATCH * TC * NPAD];   // qkv bf16 [b][3c][n] ld=NPAD
__device__ float         g_attn [(size_t)BATCH * CCH * CCH];   // scaled logits fp32
__device__ __nv_bfloat16 g_attnb[(size_t)BATCH * CCH * CCH];   // softmax bf16
__device__ __nv_bfloat16 g_fb   [(size_t)BATCH * CCH * NPAD];  // fused bf16 [c][n]
__device__ __nv_bfloat16 g_wqkv [TC * CCH];
__device__ __nv_bfloat16 g_wproj[CCH * CCH];
__device__ float g_sumsq[BATCH * 2 * CCH];                     // per-row sum of squares (q,k)
__device__ float g_inv  [BATCH * 2 * CCH];                     // invq[384], invk[384] per batch
__device__ float g_scale[CCH];
__device__ float g_shift[CCH];

// ---------------- helpers ----------------
__device__ __forceinline__ unsigned su32(const void* p) {
    return (unsigned)__cvta_generic_to_shared(p);
}
__device__ __forceinline__ unsigned pk(float a, float b) {
    __nv_bfloat162 h = __floats2bfloat162_rn(a, b);
    return *(unsigned*)&h;
}
__device__ __forceinline__ void mma_bf16(float* d, const unsigned* a, unsigned b0, unsigned b1) {
    asm volatile(
        "mma.sync.aligned.m16n8k16.row.col.f32.bf16.bf16.f32 "
        "{%0,%1,%2,%3}, {%4,%5,%6,%7}, {%8,%9}, {%0,%1,%2,%3};\n"
        : "+f"(d[0]), "+f"(d[1]), "+f"(d[2]), "+f"(d[3])
        : "r"(a[0]), "r"(a[1]), "r"(a[2]), "r"(a[3]), "r"(b0), "r"(b1));
}
#define LDSM4(r0,r1,r2,r3,addr) \
    asm volatile("ldmatrix.sync.aligned.m8n8.x4.shared.b16 {%0,%1,%2,%3}, [%4];" \
        : "=r"(r0),"=r"(r1),"=r"(r2),"=r"(r3) : "r"(addr))
#define LDSM4T(r0,r1,r2,r3,addr) \
    asm volatile("ldmatrix.sync.aligned.m8n8.x4.trans.shared.b16 {%0,%1,%2,%3}, [%4];" \
        : "=r"(r0),"=r"(r1),"=r"(r2),"=r"(r3) : "r"(addr))
#define CP16(dst, src) \
    asm volatile("cp.async.cg.shared.global [%0], [%1], 16;" :: "r"(dst), "l"(src))
#define CP_COMMIT() asm volatile("cp.async.commit_group;" ::: "memory")
#define CP_WAIT1()  asm volatile("cp.async.wait_group 1;" ::: "memory")

#define STAGE_BYTES 16384   // A 8KB + B 8KB

// ============================================================
// bf16 GEMM (mma.sync), block 128x128xK32, 3-stage cp.async ring.
// 128 threads = 4 warps (2M x 2N), warp tile 64x64.
// TRB=true : D[m,n] = sum_k A[m,k]*B[n,k]   (B K-major)
// TRB=false: D[m,n] = sum_k A[m,k]*B[k,n]   (B row-major, ldmatrix.trans)
// SQ: accumulate per-row sum(D^2) (cols < nvalid) into g_sumsq (rows < 768).
// NORM: scale D[r,c] by nrm[r]*nrm[CCH+c] (q/k inverse norms).
// ============================================================
template<bool TRB, bool BIAS, bool RES, bool OUTBF, bool GUARDN, bool NORM, bool SQ>
__global__ __launch_bounds__(128, 2)
void bgemm(const __nv_bfloat16* __restrict__ A, const __nv_bfloat16* __restrict__ B,
           void* __restrict__ Cv, const float* __restrict__ bias,
           const float* __restrict__ res, const float* __restrict__ nrm,
           int K, int lda, int ldb, int ldc, int nvalid,
           long sA, long sB, long sC, long sR)
{
    __shared__ __align__(16) unsigned char smem[3 * STAGE_BYTES];
    const unsigned sbase = su32(smem);

    const int tid = threadIdx.x;
    const int wid = tid >> 5, lane = tid & 31;
    const int wm = wid >> 1, wn = wid & 1;
    const int grp = lane >> 2, qd = lane & 3;
    const int row0 = blockIdx.y * 128;
    const int col0 = blockIdx.x * 128;
    const int z = blockIdx.z;

    const __nv_bfloat16* Ab = A + (size_t)z * sA + (size_t)row0 * lda;
    const __nv_bfloat16* Bb = TRB ? (B + (size_t)z * sB + (size_t)col0 * ldb)
                                  : (B + (size_t)z * sB + col0);

    // ---- A / NT-B loader: thread tid owns row tid (64B = 4 chunks) ----
    const int lr = tid;
    unsigned aoff[4];
    #pragma unroll
    for (int c = 0; c < 4; c++)
        aoff[c] = (unsigned)(lr * 64 + ((c ^ ((lr >> 1) & 3)) * 16));

    // ---- NN-B loader: 32 k-rows x 16 chunks (two 4KB n-halves) ----
    const int nk = tid >> 2;             // 0..31
    const int ncb = tid & 3;             // base chunk
    unsigned nboff[4];
    #pragma unroll
    for (int j = 0; j < 4; j++) {
        int nc = ncb + j * 4;
        nboff[j] = (unsigned)((nc >> 3) * 4096 + nk * 128 + (((nc & 7) ^ (nk & 7)) * 16));
    }

    const int T = K >> 5;

    // ---- fragment geometry ----
    int arow_l[4];
    #pragma unroll
    for (int mi = 0; mi < 4; mi++) arow_l[mi] = wm * 64 + mi * 16 + (lane & 15);
    const int achk = lane >> 4;
    const int bn_base = wn * 64 + ((lane >> 4) << 3) + (lane & 7);  // NT
    const int boct = (lane >> 3) & 1;                                // NT
    const int nn_kl = lane & 15;                                     // NN
    const int nn_ch = lane >> 4;                                     // NN

    float acc[4][8][4] = {};

    auto issue = [&](int s, int k0) {
        const unsigned sa = sbase + s * STAGE_BYTES;
        const unsigned sb = sa + 8192;
        #pragma unroll
        for (int c = 0; c < 4; c++)
            CP16(sa + aoff[c], Ab + (size_t)lr * lda + k0 + c * 8);
        if (TRB) {
            #pragma unroll
            for (int c = 0; c < 4; c++)
                CP16(sb + aoff[c], Bb + (size_t)lr * ldb + k0 + c * 8);
        } else {
            #pragma unroll
            for (int j = 0; j < 4; j++)
                CP16(sb + nboff[j], Bb + (size_t)(k0 + nk) * ldb + (ncb + j * 4) * 8);
        }
        CP_COMMIT();
    };

    issue(0, 0);
    issue(1, 32);

    for (int t = 0; t < T; t++) {
        CP_WAIT1();
        __syncthreads();

        if (t + 2 < T) issue((t + 2) % 3, (t + 2) << 5);
        else CP_COMMIT();

        const unsigned sa = sbase + (t % 3) * STAGE_BYTES;
        const unsigned sb = sa + 8192;

        #pragma unroll
        for (int ks = 0; ks < 2; ks++) {
            unsigned af[4][4];
            #pragma unroll
            for (int mi = 0; mi < 4; mi++) {
                unsigned addr = sa + arow_l[mi] * 64 +
                    (((ks * 2 + achk) ^ ((arow_l[mi] >> 1) & 3)) * 16);
                LDSM4(af[mi][0], af[mi][1], af[mi][2], af[mi][3], addr);
            }
            unsigned bq[4][4];
            if (TRB) {
                #pragma unroll
                for (int nj = 0; nj < 4; nj++) {
                    int nl = bn_base + nj * 16;
                    unsigned addr = sb + nl * 64 +
                        (((ks * 2 + boct) ^ ((nl >> 1) & 3)) * 16);
                    LDSM4(bq[nj][0], bq[nj][1], bq[nj][2], bq[nj][3], addr);
                }
            } else {
                const int kl = ks * 16 + nn_kl;
                const unsigned sbh = sb + wn * 4096 + kl * 128;
                #pragma unroll
                for (int nj = 0; nj < 4; nj++) {
                    unsigned addr = sbh + (((nj * 2 + nn_ch) ^ (kl & 7)) * 16);
                    LDSM4T(bq[nj][0], bq[nj][1], bq[nj][2], bq[nj][3], addr);
                }
            }
            #pragma unroll
            for (int nj = 0; nj < 4; nj++) {
                #pragma unroll
                for (int p = 0; p < 2; p++) {
                    unsigned b0 = bq[nj][p * 2], b1 = bq[nj][p * 2 + 1];
                    const int ni = nj * 2 + p;
                    #pragma unroll
                    for (int mi = 0; mi < 4; mi++)
                        mma_bf16(acc[mi][ni], af[mi], b0, b1);
                }
            }
        }
    }

    // ---- epilogue ----
    const float* nq = NORM ? (nrm + (size_t)z * 2 * CCH) : nullptr;
    const float* nkp = NORM ? (nq + CCH) : nullptr;
    const bool sq_blk = SQ && (row0 < 2 * CCH);
    #pragma unroll
    for (int mi = 0; mi < 4; mi++) {
        const int r0 = row0 + wm * 64 + mi * 16 + grp;
        const int r1 = r0 + 8;
        float bv0 = 0.0f, bv1 = 0.0f;
        if (BIAS) { bv0 = bias[r0]; bv1 = bias[r1]; }
        float sr0 = 1.0f, sr1 = 1.0f;
        if (NORM) { sr0 = nq[r0]; sr1 = nq[r1]; }
        float s0 = 0.0f, s1 = 0.0f;
        #pragma unroll
        for (int ni = 0; ni < 8; ni++) {
            const int c = col0 + wn * 64 + ni * 8 + 2 * qd;
            if (GUARDN && c >= nvalid) continue;
            float d0 = acc[mi][ni][0], d1 = acc[mi][ni][1];
            float d2 = acc[mi][ni][2], d3 = acc[mi][ni][3];
            if (NORM) {
                float c0 = nkp[c], c1 = nkp[c + 1];
                d0 *= sr0 * c0; d1 *= sr0 * c1;
                d2 *= sr1 * c0; d3 *= sr1 * c1;
            }
            d0 += bv0; d1 += bv0; d2 += bv1; d3 += bv1;
            if (RES) {
                const float* rp = res + (size_t)z * sR;
                float2 q0 = *(const float2*)&rp[(size_t)r0 * ldc + c];
                float2 q1 = *(const float2*)&rp[(size_t)r1 * ldc + c];
                d0 += q0.x; d1 += q0.y; d2 += q1.x; d3 += q1.y;
            }
            if (SQ) {
                if (sq_blk && c < nvalid) {
                    s0 += d0 * d0 + d1 * d1;
                    s1 += d2 * d2 + d3 * d3;
                }
            }
            if (OUTBF) {
                __nv_bfloat16* Cb = (__nv_bfloat16*)Cv + (size_t)z * sC;
                *(unsigned*)&Cb[(size_t)r0 * ldc + c] = pk(d0, d1);
                *(unsigned*)&Cb[(size_t)r1 * ldc + c] = pk(d2, d3);
            } else {
                float* Cf = (float*)Cv + (size_t)z * sC;
                *(float2*)&Cf[(size_t)r0 * ldc + c] = make_float2(d0, d1);
                *(float2*)&Cf[(size_t)r1 * ldc + c] = make_float2(d2, d3);
            }
        }
        if (SQ && sq_blk) {
            s0 += __shfl_xor_sync(0xffffffffu, s0, 1);
            s0 += __shfl_xor_sync(0xffffffffu, s0, 2);
            s1 += __shfl_xor_sync(0xffffffffu, s1, 1);
            s1 += __shfl_xor_sync(0xffffffffu, s1, 2);
            if (qd == 0) {
                atomicAdd(&g_sumsq[(size_t)z * 2 * CCH + r0], s0);
                atomicAdd(&g_sumsq[(size_t)z * 2 * CCH + r1], s1);
            }
        }
    }
}

// ---------------- prep / elementwise ----------------
__global__ void bn_prep(const float* __restrict__ gamma, const float* __restrict__ beta,
                        const float* __restrict__ mean,  const float* __restrict__ var) {
    int c = threadIdx.x;
    if (c < CCH) {
        float s = gamma[c] * rsqrtf(var[c] + 1e-5f);
        g_scale[c] = s;
        g_shift[c] = beta[c] - mean[c] * s;
    }
}

__global__ void f2b(const float* __restrict__ s, __nv_bfloat16* __restrict__ d, int n) {
    int i = blockIdx.x * 256 + threadIdx.x;
    if (i < n) d[i] = __float2bfloat16(s[i]);
}

// x [b][c][3136] fp32 --BN--> xT [b][n][384] bf16
__global__ void prep_xT(const float* __restrict__ x) {
    __shared__ float tl[32][33];
    const int b = blockIdx.z;
    const int n0 = blockIdx.x * 32, c0 = blockIdx.y * 32;
    const int tx = threadIdx.x, ty = threadIdx.y;
    const float* xb = x + (size_t)b * CCH * HN;
    #pragma unroll
    for (int j = 0; j < 4; j++) {
        int c = c0 + ty + j * 8;
        tl[ty + j * 8][tx] = xb[(size_t)c * HN + n0 + tx] * g_scale[c] + g_shift[c];
    }
    __syncthreads();
    __nv_bfloat16* dst = g_xT + (size_t)b * NPAD * CCH;
    #pragma unroll
    for (int j = 0; j < 4; j++) {
        int n = n0 + ty + j * 8;
        dst[(size_t)n * CCH + c0 + tx] = __float2bfloat16(tl[tx][ty + j * 8]);
    }
}

// sumsq -> inverse norms
__global__ void finalize_inv() {
    int i = blockIdx.x * 256 + threadIdx.x;
    if (i < BATCH * 2 * CCH)
        g_inv[i] = 1.0f / fmaxf(sqrtf(g_sumsq[i]), 1e-12f);
}

// softmax over last dim (384) of g_attn -> g_attnb bf16
__global__ __launch_bounds__(128)
void softmax_rows(const float* __restrict__ tptr) {
    const size_t ridx = (size_t)blockIdx.y * CCH + blockIdx.x;
    const float* row = g_attn + ridx * CCH;
    __nv_bfloat16* orow = g_attnb + ridx * CCH;
    const float t = tptr[0];
    const int tid = threadIdx.x;
    __shared__ float red[128];

    float v0 = row[tid]       * t;
    float v1 = row[tid + 128] * t;
    float v2 = row[tid + 256] * t;

    float m = fmaxf(v0, fmaxf(v1, v2));
    red[tid] = m;
    __syncthreads();
    for (int s = 64; s > 0; s >>= 1) {
        if (tid < s) red[tid] = fmaxf(red[tid], red[tid + s]);
        __syncthreads();
    }
    m = red[0];
    __syncthreads();

    float e0 = expf(v0 - m), e1 = expf(v1 - m), e2 = expf(v2 - m);
    red[tid] = e0 + e1 + e2;
    __syncthreads();
    for (int s = 64; s > 0; s >>= 1) {
        if (tid < s) red[tid] += red[tid + s];
        __syncthreads();
    }
    float inv = 1.0f / red[0];

    orow[tid]       = __float2bfloat16(e0 * inv);
    orow[tid + 128] = __float2bfloat16(e1 * inv);
    orow[tid + 256] = __float2bfloat16(e2 * inv);
}

// ---------------- host ----------------
extern "C" void kernel_launch(void* const* d_in, const int* in_sizes, int n_in,
                              void* d_out, int out_size)
{
    const float* x      = (const float*)d_in[0];
    const float* w_qkv  = (const float*)d_in[1];
    const float* b_qkv  = (const float*)d_in[2];
    const float* w_proj = (const float*)d_in[3];
    const float* b_proj = (const float*)d_in[4];
    const float* gamma  = (const float*)d_in[5];
    const float* beta   = (const float*)d_in[6];
    const float* mean   = (const float*)d_in[7];
    const float* var    = (const float*)d_in[8];
    const float* temp   = (const float*)d_in[9];
    float* out = (float*)d_out;

    __nv_bfloat16 *xT, *qkvb, *attnb, *fb, *wqkvb, *wprojb;
    float *attn, *invn, *sumsq;
    cudaGetSymbolAddress((void**)&xT,     g_xT);
    cudaGetSymbolAddress((void**)&qkvb,   g_qkvb);
    cudaGetSymbolAddress((void**)&attn,   g_attn);
    cudaGetSymbolAddress((void**)&attnb,  g_attnb);
    cudaGetSymbolAddress((void**)&fb,     g_fb);
    cudaGetSymbolAddress((void**)&wqkvb,  g_wqkv);
    cudaGetSymbolAddress((void**)&wprojb, g_wproj);
    cudaGetSymbolAddress((void**)&invn,   g_inv);
    cudaGetSymbolAddress((void**)&sumsq,  g_sumsq);

    const long sQKV = (long)TC * NPAD;
    const long sNC  = (long)NPAD * CCH;
    const long sATT = (long)CCH * CCH;
    const long sFB  = (long)CCH * NPAD;
    const long sOUT = (long)CCH * HN;

    // 0) prep
    bn_prep<<<1, CCH>>>(gamma, beta, mean, var);
    cudaMemsetAsync(sumsq, 0, (size_t)BATCH * 2 * CCH * sizeof(float));
    f2b<<<(TC*CCH + 255)/256, 256>>>(w_qkv, wqkvb, TC*CCH);
    f2b<<<(CCH*CCH + 255)/256, 256>>>(w_proj, wprojb, CCH*CCH);
    prep_xT<<<dim3(HN/32, CCH/32, BATCH), dim3(32, 8)>>>(x);

    // 1) qkv[o,n] = wqkv[o,:] . xT[n,:] + b_qkv  (NT; M=1152,N=3200,K=384)
    //    + fused per-row sum-of-squares for q,k rows (cols < 3136)
    bgemm<true, true, false, true, false, false, true>
        <<<dim3(NPAD/128, TC/128, BATCH), 128>>>(
        wqkvb, xT, qkvb, b_qkv, nullptr, nullptr,
        CCH, CCH, CCH, NPAD, HN, 0, sNC, sQKV, 0);

    // 2) finalize inverse norms
    finalize_inv<<<(BATCH*2*CCH + 255)/256, 256>>>();

    // 3) logits[c,d] = (q[c,:].k[d,:]) * invq[c]*invk[d]  (NT; K=3136), fp32
    bgemm<true, false, false, false, false, true, false>
        <<<dim3(CCH/128, CCH/128, BATCH), 128>>>(
        qkvb, qkvb + (size_t)CCH*NPAD, attn, nullptr, nullptr, invn,
        HN, NPAD, NPAD, CCH, CCH, sQKV, sQKV, sATT, 0);

    // 4) softmax -> bf16
    softmax_rows<<<dim3(CCH, BATCH), 128>>>(temp);

    // 5) fused[c,n] = attn[c,:] . v[:,n]  (NN; B = v rows of qkv), bf16
    bgemm<false, false, false, true, false, false, false>
        <<<dim3(NPAD/128, CCH/128, BATCH), 128>>>(
        attnb, qkvb + (size_t)2*CCH*NPAD, fb, nullptr, nullptr, nullptr,
        CCH, CCH, NPAD, NPAD, NPAD, sATT, sQKV, sFB, 0);

    // 6) out[o,n] = wproj[o,:] . fused[:,n] + b_proj + x  (NN; fp32, guarded)
    bgemm<false, true, true, false, true, false, false>
        <<<dim3(NPAD/128, CCH/128, BATCH), 128>>>(
        wprojb, fb, out, b_proj, x, nullptr,
        CCH, CCH, NPAD, HN, HN, 0, sFB, sOUT, sOUT);
}

// round 8
// speedup vs baseline: 1.4773x; 1.4773x over previous
#include <cuda_runtime.h>
#include <cuda_bf16.h>
#include <math.h>

#define BATCH 16
#define CCH   384
#define HN    3136
#define NPAD  3200          // HN padded to multiple of 128
#define TC    1152

// ---------------- scratch (device globals, zero-initialized) ----------------
__device__ __nv_bfloat16 g_xT   [(size_t)BATCH * NPAD * CCH];  // BN(x)^T [b][n][c]
__device__ __nv_bfloat16 g_qkvb [(size_t)BATCH * TC * NPAD];   // qkv bf16 [b][3c][n] ld=NPAD
__device__ float         g_attn [(size_t)BATCH * CCH * CCH];   // scaled logits fp32
__device__ __nv_bfloat16 g_attnb[(size_t)BATCH * CCH * CCH];   // softmax bf16
__device__ __nv_bfloat16 g_fb   [(size_t)BATCH * CCH * NPAD];  // fused bf16 [c][n]
__device__ __nv_bfloat16 g_wqkv [TC * CCH];
__device__ __nv_bfloat16 g_wproj[CCH * CCH];
__device__ float g_sumsq[BATCH * 2 * CCH];                     // per-row sum of squares (q,k)
__device__ float g_inv  [BATCH * 2 * CCH];                     // invq[384], invk[384] per batch
__device__ float g_scale[CCH];
__device__ float g_shift[CCH];

// ---------------- helpers ----------------
__device__ __forceinline__ unsigned su32(const void* p) {
    return (unsigned)__cvta_generic_to_shared(p);
}
__device__ __forceinline__ unsigned pk(float a, float b) {
    __nv_bfloat162 h = __floats2bfloat162_rn(a, b);
    return *(unsigned*)&h;
}
__device__ __forceinline__ void mma_bf16(float* d, const unsigned* a, unsigned b0, unsigned b1) {
    asm volatile(
        "mma.sync.aligned.m16n8k16.row.col.f32.bf16.bf16.f32 "
        "{%0,%1,%2,%3}, {%4,%5,%6,%7}, {%8,%9}, {%0,%1,%2,%3};\n"
        : "+f"(d[0]), "+f"(d[1]), "+f"(d[2]), "+f"(d[3])
        : "r"(a[0]), "r"(a[1]), "r"(a[2]), "r"(a[3]), "r"(b0), "r"(b1));
}
#define LDSM4(r0,r1,r2,r3,addr) \
    asm volatile("ldmatrix.sync.aligned.m8n8.x4.shared.b16 {%0,%1,%2,%3}, [%4];" \
        : "=r"(r0),"=r"(r1),"=r"(r2),"=r"(r3) : "r"(addr))
#define LDSM4T(r0,r1,r2,r3,addr) \
    asm volatile("ldmatrix.sync.aligned.m8n8.x4.trans.shared.b16 {%0,%1,%2,%3}, [%4];" \
        : "=r"(r0),"=r"(r1),"=r"(r2),"=r"(r3) : "r"(addr))
#define CP16(dst, src) \
    asm volatile("cp.async.cg.shared.global [%0], [%1], 16;" :: "r"(dst), "l"(src))
#define CP_COMMIT() asm volatile("cp.async.commit_group;" ::: "memory")
#define CP_WAIT1()  asm volatile("cp.async.wait_group 1;" ::: "memory")

#define STAGE_BYTES 16384   // A 8KB + B 8KB

// ============================================================
// bf16 GEMM (mma.sync), block 128x128xK32, 3-stage cp.async ring,
// 256 thr = 8 warps (4M x 2N), warp tile 32x64.
// TRB=true : D[m,n] = sum_k A[m,k]*B[n,k]   (B K-major, "NT")
// TRB=false: D[m,n] = sum_k A[m,k]*B[k,n]   (B row-major, "NN", ldmatrix.trans)
// NORM: scale D[r,c] by nrm[r]*nrm[CCH+c] (q/k inverse norms).
// SQ: accumulate per-row sum(D^2) (cols < nvalid) into g_sumsq (rows < 768).
// ============================================================
template<bool TRB, bool BIAS, bool RES, bool OUTBF, bool GUARDN, bool NORM, bool SQ>
__global__ __launch_bounds__(256, 2)
void bgemm(const __nv_bfloat16* __restrict__ A, const __nv_bfloat16* __restrict__ B,
           void* __restrict__ Cv, const float* __restrict__ bias,
           const float* __restrict__ res, const float* __restrict__ nrm,
           int K, int lda, int ldb, int ldc, int nvalid,
           long sA, long sB, long sC, long sR)
{
    __shared__ __align__(16) unsigned char smem[3 * STAGE_BYTES];
    const unsigned sbase = su32(smem);

    const int tid = threadIdx.x;
    const int wid = tid >> 5, lane = tid & 31;
    const int wm = wid >> 1, wn = wid & 1;
    const int grp = lane >> 2, qd = lane & 3;
    const int row0 = blockIdx.y * 128;
    const int col0 = blockIdx.x * 128;
    const int z = blockIdx.z;

    const __nv_bfloat16* Ab = A + (size_t)z * sA + (size_t)row0 * lda;
    const __nv_bfloat16* Bb = TRB ? (B + (size_t)z * sB + (size_t)col0 * ldb)
                                  : (B + (size_t)z * sB + col0);

    // ---- A loader geometry (rows of 64B, 4 chunks) ----
    const int lr = tid >> 2, lc = tid & 3;
    const unsigned aoff1 = (unsigned)(lr * 64 + ((lc ^ ((lr >> 1) & 3)) * 16));
    const int lr2 = lr + 64;
    const unsigned aoff2 = (unsigned)(lr2 * 64 + ((lc ^ ((lr2 >> 1) & 3)) * 16));

    // ---- NN B loader geometry (32 k-rows x 16 chunks -> 2 halves) ----
    const int nk1 = tid >> 4, nc1 = tid & 15;
    const unsigned nboff1 = (unsigned)((nc1 >> 3) * 4096 + nk1 * 128 + (((nc1 & 7) ^ (nk1 & 7)) * 16));
    const int nk2 = (tid + 256) >> 4, nc2 = tid & 15;
    const unsigned nboff2 = (unsigned)((nc2 >> 3) * 4096 + nk2 * 128 + (((nc2 & 7) ^ (nk2 & 7)) * 16));

    const int T = K >> 5;

    // ---- fragment geometry ----
    int arow_l[2];
    #pragma unroll
    for (int mi = 0; mi < 2; mi++) arow_l[mi] = wm * 32 + mi * 16 + (lane & 15);
    const int achk = lane >> 4;
    // NT B frag
    const int bn_base = wn * 64 + ((lane >> 4) << 3) + (lane & 7);
    const int boct = (lane >> 3) & 1;
    // NN B frag
    const int nn_kl = lane & 15;
    const int nn_ch = lane >> 4;

    float acc[2][8][4] = {};

    auto issue = [&](int s, int k0) {
        const unsigned sa = sbase + s * STAGE_BYTES;
        const unsigned sb = sa + 8192;
        CP16(sa + aoff1, Ab + (size_t)lr  * lda + k0 + lc * 8);
        CP16(sa + aoff2, Ab + (size_t)lr2 * lda + k0 + lc * 8);
        if (TRB) {
            CP16(sb + aoff1, Bb + (size_t)lr  * ldb + k0 + lc * 8);
            CP16(sb + aoff2, Bb + (size_t)lr2 * ldb + k0 + lc * 8);
        } else {
            CP16(sb + nboff1, Bb + (size_t)(k0 + nk1) * ldb + nc1 * 8);
            CP16(sb + nboff2, Bb + (size_t)(k0 + nk2) * ldb + nc2 * 8);
        }
        CP_COMMIT();
    };

    issue(0, 0);
    issue(1, 32);

    for (int t = 0; t < T; t++) {
        CP_WAIT1();
        __syncthreads();

        if (t + 2 < T) issue((t + 2) % 3, (t + 2) << 5);
        else CP_COMMIT();

        const unsigned sa = sbase + (t % 3) * STAGE_BYTES;
        const unsigned sb = sa + 8192;

        #pragma unroll
        for (int ks = 0; ks < 2; ks++) {
            unsigned af[2][4];
            #pragma unroll
            for (int mi = 0; mi < 2; mi++) {
                unsigned addr = sa + arow_l[mi] * 64 +
                    (((ks * 2 + achk) ^ ((arow_l[mi] >> 1) & 3)) * 16);
                LDSM4(af[mi][0], af[mi][1], af[mi][2], af[mi][3], addr);
            }
            unsigned bq[4][4];
            if (TRB) {
                #pragma unroll
                for (int nj = 0; nj < 4; nj++) {
                    int nl = bn_base + nj * 16;
                    unsigned addr = sb + nl * 64 +
                        (((ks * 2 + boct) ^ ((nl >> 1) & 3)) * 16);
                    LDSM4(bq[nj][0], bq[nj][1], bq[nj][2], bq[nj][3], addr);
                }
            } else {
                const int kl = ks * 16 + nn_kl;
                const unsigned sbh = sb + wn * 4096 + kl * 128;
                #pragma unroll
                for (int nj = 0; nj < 4; nj++) {
                    unsigned addr = sbh + (((nj * 2 + nn_ch) ^ (kl & 7)) * 16);
                    LDSM4T(bq[nj][0], bq[nj][1], bq[nj][2], bq[nj][3], addr);
                }
            }
            #pragma unroll
            for (int nj = 0; nj < 4; nj++) {
                #pragma unroll
                for (int p = 0; p < 2; p++) {
                    unsigned b0 = bq[nj][p * 2], b1 = bq[nj][p * 2 + 1];
                    const int ni = nj * 2 + p;
                    #pragma unroll
                    for (int mi = 0; mi < 2; mi++)
                        mma_bf16(acc[mi][ni], af[mi], b0, b1);
                }
            }
        }
    }

    // ---- epilogue ----
    const float* nq = NORM ? (nrm + (size_t)z * 2 * CCH) : nullptr;
    const float* nkp = NORM ? (nq + CCH) : nullptr;
    const bool sq_blk = SQ && (row0 < 2 * CCH);
    #pragma unroll
    for (int mi = 0; mi < 2; mi++) {
        const int r0 = row0 + wm * 32 + mi * 16 + grp;
        const int r1 = r0 + 8;
        float bv0 = 0.0f, bv1 = 0.0f;
        if (BIAS) { bv0 = bias[r0]; bv1 = bias[r1]; }
        float sr0 = 1.0f, sr1 = 1.0f;
        if (NORM) { sr0 = nq[r0]; sr1 = nq[r1]; }
        float s0 = 0.0f, s1 = 0.0f;
        #pragma unroll
        for (int ni = 0; ni < 8; ni++) {
            const int c = col0 + wn * 64 + ni * 8 + 2 * qd;
            if (GUARDN && c >= nvalid) continue;
            float d0 = acc[mi][ni][0], d1 = acc[mi][ni][1];
            float d2 = acc[mi][ni][2], d3 = acc[mi][ni][3];
            if (NORM) {
                float c0 = nkp[c], c1 = nkp[c + 1];
                d0 *= sr0 * c0; d1 *= sr0 * c1;
                d2 *= sr1 * c0; d3 *= sr1 * c1;
            }
            d0 += bv0; d1 += bv0; d2 += bv1; d3 += bv1;
            if (RES) {
                const float* rp = res + (size_t)z * sR;
                float2 q0 = *(const float2*)&rp[(size_t)r0 * ldc + c];
                float2 q1 = *(const float2*)&rp[(size_t)r1 * ldc + c];
                d0 += q0.x; d1 += q0.y; d2 += q1.x; d3 += q1.y;
            }
            if (SQ) {
                if (sq_blk && c < nvalid) {
                    s0 += d0 * d0 + d1 * d1;
                    s1 += d2 * d2 + d3 * d3;
                }
            }
            if (OUTBF) {
                __nv_bfloat16* Cb = (__nv_bfloat16*)Cv + (size_t)z * sC;
                *(unsigned*)&Cb[(size_t)r0 * ldc + c] = pk(d0, d1);
                *(unsigned*)&Cb[(size_t)r1 * ldc + c] = pk(d2, d3);
            } else {
                float* Cf = (float*)Cv + (size_t)z * sC;
                *(float2*)&Cf[(size_t)r0 * ldc + c] = make_float2(d0, d1);
                *(float2*)&Cf[(size_t)r1 * ldc + c] = make_float2(d2, d3);
            }
        }
        if (SQ && sq_blk) {
            s0 += __shfl_xor_sync(0xffffffffu, s0, 1);
            s0 += __shfl_xor_sync(0xffffffffu, s0, 2);
            s1 += __shfl_xor_sync(0xffffffffu, s1, 1);
            s1 += __shfl_xor_sync(0xffffffffu, s1, 2);
            if (qd == 0) {
                atomicAdd(&g_sumsq[(size_t)z * 2 * CCH + r0], s0);
                atomicAdd(&g_sumsq[(size_t)z * 2 * CCH + r1], s1);
            }
        }
    }
}

// ---------------- prep / elementwise ----------------
__global__ void bn_prep(const float* __restrict__ gamma, const float* __restrict__ beta,
                        const float* __restrict__ mean,  const float* __restrict__ var) {
    int c = threadIdx.x;
    if (c < CCH) {
        float s = gamma[c] * rsqrtf(var[c] + 1e-5f);
        g_scale[c] = s;
        g_shift[c] = beta[c] - mean[c] * s;
    }
}

__global__ void f2b(const float* __restrict__ s, __nv_bfloat16* __restrict__ d, int n) {
    int i = blockIdx.x * 256 + threadIdx.x;
    if (i < n) d[i] = __float2bfloat16(s[i]);
}

// x [b][c][3136] fp32 --BN--> xT [b][n][384] bf16
__global__ void prep_xT(const float* __restrict__ x) {
    __shared__ float tl[32][33];
    const int b = blockIdx.z;
    const int n0 = blockIdx.x * 32, c0 = blockIdx.y * 32;
    const int tx = threadIdx.x, ty = threadIdx.y;
    const float* xb = x + (size_t)b * CCH * HN;
    #pragma unroll
    for (int j = 0; j < 4; j++) {
        int c = c0 + ty + j * 8;
        tl[ty + j * 8][tx] = xb[(size_t)c * HN + n0 + tx] * g_scale[c] + g_shift[c];
    }
    __syncthreads();
    __nv_bfloat16* dst = g_xT + (size_t)b * NPAD * CCH;
    #pragma unroll
    for (int j = 0; j < 4; j++) {
        int n = n0 + ty + j * 8;
        dst[(size_t)n * CCH + c0 + tx] = __float2bfloat16(tl[tx][ty + j * 8]);
    }
}

// sumsq -> inverse norms
__global__ void finalize_inv() {
    int i = blockIdx.x * 256 + threadIdx.x;
    if (i < BATCH * 2 * CCH)
        g_inv[i] = 1.0f / fmaxf(sqrtf(g_sumsq[i]), 1e-12f);
}

// softmax over last dim (384) of g_attn -> g_attnb bf16
__global__ __launch_bounds__(128)
void softmax_rows(const float* __restrict__ tptr) {
    const size_t ridx = (size_t)blockIdx.y * CCH + blockIdx.x;
    const float* row = g_attn + ridx * CCH;
    __nv_bfloat16* orow = g_attnb + ridx * CCH;
    const float t = tptr[0];
    const int tid = threadIdx.x;
    __shared__ float red[128];

    float v0 = row[tid]       * t;
    float v1 = row[tid + 128] * t;
    float v2 = row[tid + 256] * t;

    float m = fmaxf(v0, fmaxf(v1, v2));
    red[tid] = m;
    __syncthreads();
    for (int s = 64; s > 0; s >>= 1) {
        if (tid < s) red[tid] = fmaxf(red[tid], red[tid + s]);
        __syncthreads();
    }
    m = red[0];
    __syncthreads();

    float e0 = expf(v0 - m), e1 = expf(v1 - m), e2 = expf(v2 - m);
    red[tid] = e0 + e1 + e2;
    __syncthreads();
    for (int s = 64; s > 0; s >>= 1) {
        if (tid < s) red[tid] += red[tid + s];
        __syncthreads();
    }
    float inv = 1.0f / red[0];

    orow[tid]       = __float2bfloat16(e0 * inv);
    orow[tid + 128] = __float2bfloat16(e1 * inv);
    orow[tid + 256] = __float2bfloat16(e2 * inv);
}

// ---------------- host ----------------
extern "C" void kernel_launch(void* const* d_in, const int* in_sizes, int n_in,
                              void* d_out, int out_size)
{
    const float* x      = (const float*)d_in[0];
    const float* w_qkv  = (const float*)d_in[1];
    const float* b_qkv  = (const float*)d_in[2];
    const float* w_proj = (const float*)d_in[3];
    const float* b_proj = (const float*)d_in[4];
    const float* gamma  = (const float*)d_in[5];
    const float* beta   = (const float*)d_in[6];
    const float* mean   = (const float*)d_in[7];
    const float* var    = (const float*)d_in[8];
    const float* temp   = (const float*)d_in[9];
    float* out = (float*)d_out;

    __nv_bfloat16 *xT, *qkvb, *attnb, *fb, *wqkvb, *wprojb;
    float *attn, *invn, *sumsq;
    cudaGetSymbolAddress((void**)&xT,     g_xT);
    cudaGetSymbolAddress((void**)&qkvb,   g_qkvb);
    cudaGetSymbolAddress((void**)&attn,   g_attn);
    cudaGetSymbolAddress((void**)&attnb,  g_attnb);
    cudaGetSymbolAddress((void**)&fb,     g_fb);
    cudaGetSymbolAddress((void**)&wqkvb,  g_wqkv);
    cudaGetSymbolAddress((void**)&wprojb, g_wproj);
    cudaGetSymbolAddress((void**)&invn,   g_inv);
    cudaGetSymbolAddress((void**)&sumsq,  g_sumsq);

    const long sQKV = (long)TC * NPAD;
    const long sNC  = (long)NPAD * CCH;
    const long sATT = (long)CCH * CCH;
    const long sFB  = (long)CCH * NPAD;
    const long sOUT = (long)CCH * HN;

    // 0) prep
    bn_prep<<<1, CCH>>>(gamma, beta, mean, var);
    cudaMemsetAsync(sumsq, 0, (size_t)BATCH * 2 * CCH * sizeof(float));
    f2b<<<(TC*CCH + 255)/256, 256>>>(w_qkv, wqkvb, TC*CCH);
    f2b<<<(CCH*CCH + 255)/256, 256>>>(w_proj, wprojb, CCH*CCH);
    prep_xT<<<dim3(HN/32, CCH/32, BATCH), dim3(32, 8)>>>(x);

    // 1) qkv[o,n] = wqkv[o,:] . xT[n,:] + b_qkv  (NT; M=1152,N=3200,K=384)
    //    + fused per-row sum-of-squares for q,k rows (cols < 3136)
    bgemm<true, true, false, true, false, false, true>
        <<<dim3(NPAD/128, TC/128, BATCH), 256>>>(
        wqkvb, xT, qkvb, b_qkv, nullptr, nullptr,
        CCH, CCH, CCH, NPAD, HN, 0, sNC, sQKV, 0);

    // 2) finalize inverse norms
    finalize_inv<<<(BATCH*2*CCH + 255)/256, 256>>>();

    // 3) logits[c,d] = (q[c,:].k[d,:]) * invq[c]*invk[d]  (NT; K=3136), fp32
    bgemm<true, false, false, false, false, true, false>
        <<<dim3(CCH/128, CCH/128, BATCH), 256>>>(
        qkvb, qkvb + (size_t)CCH*NPAD, attn, nullptr, nullptr, invn,
        HN, NPAD, NPAD, CCH, CCH, sQKV, sQKV, sATT, 0);

    // 4) softmax -> bf16
    softmax_rows<<<dim3(CCH, BATCH), 128>>>(temp);

    // 5) fused[c,n] = attn[c,:] . v[:,n]  (NN; B = v rows of qkv), bf16
    bgemm<false, false, false, true, false, false, false>
        <<<dim3(NPAD/128, CCH/128, BATCH), 256>>>(
        attnb, qkvb + (size_t)2*CCH*NPAD, fb, nullptr, nullptr, nullptr,
        CCH, CCH, NPAD, NPAD, NPAD, sATT, sQKV, sFB, 0);

    // 6) out[o,n] = wproj[o,:] . fused[:,n] + b_proj + x  (NN; fp32, guarded)
    bgemm<false, true, true, false, true, false, false>
        <<<dim3(NPAD/128, CCH/128, BATCH), 256>>>(
        wprojb, fb, out, b_proj, x, nullptr,
        CCH, CCH, NPAD, HN, HN, 0, sFB, sOUT, sOUT);
}

// round 9
// speedup vs baseline: 1.4803x; 1.0021x over previous
#include <cuda_runtime.h>
#include <cuda_bf16.h>
#include <math.h>

#define BATCH 16
#define CCH   384
#define HN    3136
#define NPAD  3200          // HN padded to multiple of 128
#define TC    1152
#define KSPL  7             // split-K factor for logits GEMM (3136 = 7*448)
#define KCH   448           // K per split part
#define PSTR  ((size_t)BATCH * CCH * CCH)   // partial-buffer stride

// ---------------- scratch (device globals, zero-initialized) ----------------
__device__ __nv_bfloat16 g_xT   [(size_t)BATCH * NPAD * CCH];  // BN(x)^T [b][n][c]
__device__ __nv_bfloat16 g_qkvb [(size_t)BATCH * TC * NPAD];   // qkv bf16 [b][3c][n] ld=NPAD
__device__ float         g_attn [KSPL * PSTR];                 // logits partials fp32
__device__ __nv_bfloat16 g_attnb[(size_t)BATCH * CCH * CCH];   // softmax bf16
__device__ __nv_bfloat16 g_fb   [(size_t)BATCH * CCH * NPAD];  // fused bf16 [c][n]
__device__ __nv_bfloat16 g_wqkv [TC * CCH];
__device__ __nv_bfloat16 g_wproj[CCH * CCH];
__device__ float g_sumsq[BATCH * 2 * CCH];                     // per-row sum of squares (q,k)
__device__ float g_inv  [BATCH * 2 * CCH];                     // invq[384], invk[384] per batch
__device__ float g_scale[CCH];
__device__ float g_shift[CCH];

// ---------------- helpers ----------------
__device__ __forceinline__ unsigned su32(const void* p) {
    return (unsigned)__cvta_generic_to_shared(p);
}
__device__ __forceinline__ unsigned pk(float a, float b) {
    __nv_bfloat162 h = __floats2bfloat162_rn(a, b);
    return *(unsigned*)&h;
}
__device__ __forceinline__ void mma_bf16(float* d, const unsigned* a, unsigned b0, unsigned b1) {
    asm volatile(
        "mma.sync.aligned.m16n8k16.row.col.f32.bf16.bf16.f32 "
        "{%0,%1,%2,%3}, {%4,%5,%6,%7}, {%8,%9}, {%0,%1,%2,%3};\n"
        : "+f"(d[0]), "+f"(d[1]), "+f"(d[2]), "+f"(d[3])
        : "r"(a[0]), "r"(a[1]), "r"(a[2]), "r"(a[3]), "r"(b0), "r"(b1));
}
#define LDSM4(r0,r1,r2,r3,addr) \
    asm volatile("ldmatrix.sync.aligned.m8n8.x4.shared.b16 {%0,%1,%2,%3}, [%4];" \
        : "=r"(r0),"=r"(r1),"=r"(r2),"=r"(r3) : "r"(addr))
#define LDSM4T(r0,r1,r2,r3,addr) \
    asm volatile("ldmatrix.sync.aligned.m8n8.x4.trans.shared.b16 {%0,%1,%2,%3}, [%4];" \
        : "=r"(r0),"=r"(r1),"=r"(r2),"=r"(r3) : "r"(addr))
#define CP16(dst, src) \
    asm volatile("cp.async.cg.shared.global [%0], [%1], 16;" :: "r"(dst), "l"(src))
#define CP_COMMIT() asm volatile("cp.async.commit_group;" ::: "memory")
#define CP_WAIT1()  asm volatile("cp.async.wait_group 1;" ::: "memory")

#define STAGE_BYTES 16384   // A 8KB + B 8KB

// ============================================================
// bf16 GEMM (mma.sync), block 128x128xK32, 3-stage cp.async ring,
// 256 thr = 8 warps (4M x 2N), warp tile 32x64.
// KSP>1: blockIdx.z = zb*KSP + part; A,B advance part*K along k;
//        C goes to partial buffer at part*sPart.
// TRB=true : D[m,n] = sum_k A[m,k]*B[n,k]   (B K-major)
// TRB=false: D[m,n] = sum_k A[m,k]*B[k,n]   (B row-major, ldmatrix.trans)
// SQ: accumulate per-row sum(D^2) (cols < nvalid) into g_sumsq (rows < 768).
// ============================================================
template<int KSP, bool TRB, bool BIAS, bool RES, bool OUTBF, bool GUARDN, bool SQ>
__global__ __launch_bounds__(256, 2)
void bgemm(const __nv_bfloat16* __restrict__ A, const __nv_bfloat16* __restrict__ B,
           void* __restrict__ Cv, const float* __restrict__ bias,
           const float* __restrict__ res,
           int K, int lda, int ldb, int ldc, int nvalid,
           long sA, long sB, long sC, long sR, long sPart)
{
    __shared__ __align__(16) unsigned char smem[3 * STAGE_BYTES];
    const unsigned sbase = su32(smem);

    const int tid = threadIdx.x;
    const int wid = tid >> 5, lane = tid & 31;
    const int wm = wid >> 1, wn = wid & 1;
    const int grp = lane >> 2, qd = lane & 3;
    const int row0 = blockIdx.y * 128;
    const int col0 = blockIdx.x * 128;
    int z = blockIdx.z;
    int part = 0;
    if (KSP > 1) { part = z % KSP; z /= KSP; }

    const __nv_bfloat16* Az = A + (size_t)z * sA + (size_t)part * K;
    const __nv_bfloat16* Bz = B + (size_t)z * sB + (size_t)part * K;
    const __nv_bfloat16* Ab = Az + (size_t)row0 * lda;
    const __nv_bfloat16* Bb = TRB ? (Bz + (size_t)col0 * ldb) : (Bz + col0);

    // ---- A loader geometry (rows of 64B, 4 chunks) ----
    const int lr = tid >> 2, lc = tid & 3;
    const unsigned aoff1 = (unsigned)(lr * 64 + ((lc ^ ((lr >> 1) & 3)) * 16));
    const int lr2 = lr + 64;
    const unsigned aoff2 = (unsigned)(lr2 * 64 + ((lc ^ ((lr2 >> 1) & 3)) * 16));

    // ---- NN B loader geometry (32 k-rows x 16 chunks -> 2 halves) ----
    const int nk1 = tid >> 4, nc1 = tid & 15;
    const unsigned nboff1 = (unsigned)((nc1 >> 3) * 4096 + nk1 * 128 + (((nc1 & 7) ^ (nk1 & 7)) * 16));
    const int nk2 = (tid + 256) >> 4, nc2 = tid & 15;
    const unsigned nboff2 = (unsigned)((nc2 >> 3) * 4096 + nk2 * 128 + (((nc2 & 7) ^ (nk2 & 7)) * 16));

    const int T = K >> 5;

    // ---- fragment geometry ----
    int arow_l[2];
    #pragma unroll
    for (int mi = 0; mi < 2; mi++) arow_l[mi] = wm * 32 + mi * 16 + (lane & 15);
    const int achk = lane >> 4;
    const int bn_base = wn * 64 + ((lane >> 4) << 3) + (lane & 7);
    const int boct = (lane >> 3) & 1;
    const int nn_kl = lane & 15;
    const int nn_ch = lane >> 4;

    float acc[2][8][4] = {};

    auto issue = [&](int s, int k0) {
        const unsigned sa = sbase + s * STAGE_BYTES;
        const unsigned sb = sa + 8192;
        CP16(sa + aoff1, Ab + (size_t)lr  * lda + k0 + lc * 8);
        CP16(sa + aoff2, Ab + (size_t)lr2 * lda + k0 + lc * 8);
        if (TRB) {
            CP16(sb + aoff1, Bb + (size_t)lr  * ldb + k0 + lc * 8);
            CP16(sb + aoff2, Bb + (size_t)lr2 * ldb + k0 + lc * 8);
        } else {
            CP16(sb + nboff1, Bb + (size_t)(k0 + nk1) * ldb + nc1 * 8);
            CP16(sb + nboff2, Bb + (size_t)(k0 + nk2) * ldb + nc2 * 8);
        }
        CP_COMMIT();
    };

    issue(0, 0);
    issue(1, 32);

    for (int t = 0; t < T; t++) {
        CP_WAIT1();
        __syncthreads();

        if (t + 2 < T) issue((t + 2) % 3, (t + 2) << 5);
        else CP_COMMIT();

        const unsigned sa = sbase + (t % 3) * STAGE_BYTES;
        const unsigned sb = sa + 8192;

        #pragma unroll
        for (int ks = 0; ks < 2; ks++) {
            unsigned af[2][4];
            #pragma unroll
            for (int mi = 0; mi < 2; mi++) {
                unsigned addr = sa + arow_l[mi] * 64 +
                    (((ks * 2 + achk) ^ ((arow_l[mi] >> 1) & 3)) * 16);
                LDSM4(af[mi][0], af[mi][1], af[mi][2], af[mi][3], addr);
            }
            unsigned bq[4][4];
            if (TRB) {
                #pragma unroll
                for (int nj = 0; nj < 4; nj++) {
                    int nl = bn_base + nj * 16;
                    unsigned addr = sb + nl * 64 +
                        (((ks * 2 + boct) ^ ((nl >> 1) & 3)) * 16);
                    LDSM4(bq[nj][0], bq[nj][1], bq[nj][2], bq[nj][3], addr);
                }
            } else {
                const int kl = ks * 16 + nn_kl;
                const unsigned sbh = sb + wn * 4096 + kl * 128;
                #pragma unroll
                for (int nj = 0; nj < 4; nj++) {
                    unsigned addr = sbh + (((nj * 2 + nn_ch) ^ (kl & 7)) * 16);
                    LDSM4T(bq[nj][0], bq[nj][1], bq[nj][2], bq[nj][3], addr);
                }
            }
            #pragma unroll
            for (int nj = 0; nj < 4; nj++) {
                #pragma unroll
                for (int p = 0; p < 2; p++) {
                    unsigned b0 = bq[nj][p * 2], b1 = bq[nj][p * 2 + 1];
                    const int ni = nj * 2 + p;
                    #pragma unroll
                    for (int mi = 0; mi < 2; mi++)
                        mma_bf16(acc[mi][ni], af[mi], b0, b1);
                }
            }
        }
    }

    // ---- epilogue ----
    const bool sq_blk = SQ && (row0 < 2 * CCH);
    #pragma unroll
    for (int mi = 0; mi < 2; mi++) {
        const int r0 = row0 + wm * 32 + mi * 16 + grp;
        const int r1 = r0 + 8;
        float bv0 = 0.0f, bv1 = 0.0f;
        if (BIAS) { bv0 = bias[r0]; bv1 = bias[r1]; }
        float s0 = 0.0f, s1 = 0.0f;
        #pragma unroll
        for (int ni = 0; ni < 8; ni++) {
            const int c = col0 + wn * 64 + ni * 8 + 2 * qd;
            if (GUARDN && c >= nvalid) continue;
            float d0 = acc[mi][ni][0] + bv0, d1 = acc[mi][ni][1] + bv0;
            float d2 = acc[mi][ni][2] + bv1, d3 = acc[mi][ni][3] + bv1;
            if (RES) {
                const float* rp = res + (size_t)z * sR;
                float2 q0 = *(const float2*)&rp[(size_t)r0 * ldc + c];
                float2 q1 = *(const float2*)&rp[(size_t)r1 * ldc + c];
                d0 += q0.x; d1 += q0.y; d2 += q1.x; d3 += q1.y;
            }
            if (SQ) {
                if (sq_blk && c < nvalid) {
                    s0 += d0 * d0 + d1 * d1;
                    s1 += d2 * d2 + d3 * d3;
                }
            }
            if (OUTBF) {
                __nv_bfloat16* Cb = (__nv_bfloat16*)Cv + (size_t)z * sC;
                *(unsigned*)&Cb[(size_t)r0 * ldc + c] = pk(d0, d1);
                *(unsigned*)&Cb[(size_t)r1 * ldc + c] = pk(d2, d3);
            } else {
                float* Cf = (float*)Cv + (size_t)z * sC + (size_t)part * sPart;
                *(float2*)&Cf[(size_t)r0 * ldc + c] = make_float2(d0, d1);
                *(float2*)&Cf[(size_t)r1 * ldc + c] = make_float2(d2, d3);
            }
        }
        if (SQ && sq_blk) {
            s0 += __shfl_xor_sync(0xffffffffu, s0, 1);
            s0 += __shfl_xor_sync(0xffffffffu, s0, 2);
            s1 += __shfl_xor_sync(0xffffffffu, s1, 1);
            s1 += __shfl_xor_sync(0xffffffffu, s1, 2);
            if (qd == 0) {
                atomicAdd(&g_sumsq[(size_t)z * 2 * CCH + r0], s0);
                atomicAdd(&g_sumsq[(size_t)z * 2 * CCH + r1], s1);
            }
        }
    }
}

// ---------------- prep / elementwise ----------------
__global__ void bn_prep(const float* __restrict__ gamma, const float* __restrict__ beta,
                        const float* __restrict__ mean,  const float* __restrict__ var) {
    int c = threadIdx.x;
    if (c < CCH) {
        float s = gamma[c] * rsqrtf(var[c] + 1e-5f);
        g_scale[c] = s;
        g_shift[c] = beta[c] - mean[c] * s;
    }
}

__global__ void f2b(const float* __restrict__ s, __nv_bfloat16* __restrict__ d, int n) {
    int i = blockIdx.x * 256 + threadIdx.x;
    if (i < n) d[i] = __float2bfloat16(s[i]);
}

// x [b][c][3136] fp32 --BN--> xT [b][n][384] bf16.  64x64 tiles, vectorized.
__global__ __launch_bounds__(256)
void prep_xT(const float* __restrict__ x) {
    __shared__ float tl[64][65];
    const int b = blockIdx.z;
    const int n0 = blockIdx.x * 64, c0 = blockIdx.y * 64;
    const int tid = threadIdx.x;
    const float* xb = x + (size_t)b * CCH * HN;

    // load: 64 c-rows x 16 float4 (64 n), 4 per thread
    {
        const int cl = tid >> 2;                 // 0..63
        const float s = g_scale[c0 + cl], h = g_shift[c0 + cl];
        const float* src = xb + (size_t)(c0 + cl) * HN + n0;
        #pragma unroll
        for (int j = 0; j < 4; j++) {
            int f = (tid & 3) + j * 4;           // 0..15
            float4 v = *(const float4*)(src + f * 4);
            tl[cl][f * 4 + 0] = v.x * s + h;
            tl[cl][f * 4 + 1] = v.y * s + h;
            tl[cl][f * 4 + 2] = v.z * s + h;
            tl[cl][f * 4 + 3] = v.w * s + h;
        }
    }
    __syncthreads();

    // store: 64 n-rows x 8 uint4 (64 c as bf16), 2 per thread
    {
        const int nl = tid >> 2;                 // 0..63
        __nv_bfloat16* dst = g_xT + (size_t)b * NPAD * CCH + (size_t)(n0 + nl) * CCH + c0;
        #pragma unroll
        for (int j = 0; j < 2; j++) {
            int u = (tid & 3) + j * 4;           // 0..7
            int cc = u * 8;
            uint4 o;
            o.x = pk(tl[cc + 0][nl], tl[cc + 1][nl]);
            o.y = pk(tl[cc + 2][nl], tl[cc + 3][nl]);
            o.z = pk(tl[cc + 4][nl], tl[cc + 5][nl]);
            o.w = pk(tl[cc + 6][nl], tl[cc + 7][nl]);
            *(uint4*)(dst + cc) = o;
        }
    }
}

// sumsq -> inverse norms
__global__ void finalize_inv() {
    int i = blockIdx.x * 256 + threadIdx.x;
    if (i < BATCH * 2 * CCH)
        g_inv[i] = 1.0f / fmaxf(sqrtf(g_sumsq[i]), 1e-12f);
}

// softmax over last dim (384): sums KSPL partials, applies t*invq[c]*invk[d]
__global__ __launch_bounds__(128)
void softmax_rows(const float* __restrict__ tptr) {
    const int b = blockIdx.y, cc = blockIdx.x;
    const size_t ridx = (size_t)b * CCH + cc;
    const float* row = g_attn + ridx * CCH;
    __nv_bfloat16* orow = g_attnb + ridx * CCH;
    const int tid = threadIdx.x;
    __shared__ float red[128];

    const float tq = tptr[0] * g_inv[(size_t)b * 2 * CCH + cc];
    const float* ik = g_inv + (size_t)b * 2 * CCH + CCH;

    float v0 = 0.0f, v1 = 0.0f, v2 = 0.0f;
    #pragma unroll
    for (int p = 0; p < KSPL; p++) {
        const float* rp = row + (size_t)p * PSTR;
        v0 += rp[tid];
        v1 += rp[tid + 128];
        v2 += rp[tid + 256];
    }
    v0 *= tq * ik[tid];
    v1 *= tq * ik[tid + 128];
    v2 *= tq * ik[tid + 256];

    float m = fmaxf(v0, fmaxf(v1, v2));
    red[tid] = m;
    __syncthreads();
    for (int s = 64; s > 0; s >>= 1) {
        if (tid < s) red[tid] = fmaxf(red[tid], red[tid + s]);
        __syncthreads();
    }
    m = red[0];
    __syncthreads();

    float e0 = expf(v0 - m), e1 = expf(v1 - m), e2 = expf(v2 - m);
    red[tid] = e0 + e1 + e2;
    __syncthreads();
    for (int s = 64; s > 0; s >>= 1) {
        if (tid < s) red[tid] += red[tid + s];
        __syncthreads();
    }
    float inv = 1.0f / red[0];

    orow[tid]       = __float2bfloat16(e0 * inv);
    orow[tid + 128] = __float2bfloat16(e1 * inv);
    orow[tid + 256] = __float2bfloat16(e2 * inv);
}

// ---------------- host ----------------
extern "C" void kernel_launch(void* const* d_in, const int* in_sizes, int n_in,
                              void* d_out, int out_size)
{
    const float* x      = (const float*)d_in[0];
    const float* w_qkv  = (const float*)d_in[1];
    const float* b_qkv  = (const float*)d_in[2];
    const float* w_proj = (const float*)d_in[3];
    const float* b_proj = (const float*)d_in[4];
    const float* gamma  = (const float*)d_in[5];
    const float* beta   = (const float*)d_in[6];
    const float* mean   = (const float*)d_in[7];
    const float* var    = (const float*)d_in[8];
    const float* temp   = (const float*)d_in[9];
    float* out = (float*)d_out;

    __nv_bfloat16 *qkvb, *attnb, *fb, *wqkvb, *wprojb, *xT;
    float *attn, *sumsq;
    cudaGetSymbolAddress((void**)&xT,     g_xT);
    cudaGetSymbolAddress((void**)&qkvb,   g_qkvb);
    cudaGetSymbolAddress((void**)&attn,   g_attn);
    cudaGetSymbolAddress((void**)&attnb,  g_attnb);
    cudaGetSymbolAddress((void**)&fb,     g_fb);
    cudaGetSymbolAddress((void**)&wqkvb,  g_wqkv);
    cudaGetSymbolAddress((void**)&wprojb, g_wproj);
    cudaGetSymbolAddress((void**)&sumsq,  g_sumsq);

    const long sQKV = (long)TC * NPAD;
    const long sNC  = (long)NPAD * CCH;
    const long sATT = (long)CCH * CCH;
    const long sFB  = (long)CCH * NPAD;
    const long sOUT = (long)CCH * HN;

    // 0) prep
    bn_prep<<<1, CCH>>>(gamma, beta, mean, var);
    cudaMemsetAsync(sumsq, 0, (size_t)BATCH * 2 * CCH * sizeof(float));
    f2b<<<(TC*CCH + 255)/256, 256>>>(w_qkv, wqkvb, TC*CCH);
    f2b<<<(CCH*CCH + 255)/256, 256>>>(w_proj, wprojb, CCH*CCH);
    prep_xT<<<dim3(HN/64, CCH/64, BATCH), 256>>>(x);

    // 1) qkv = wqkv . xT^T + b_qkv (NT) + fused q/k sum-of-squares
    bgemm<1, true, true, false, true, false, true>
        <<<dim3(NPAD/128, TC/128, BATCH), 256>>>(
        wqkvb, xT, qkvb, b_qkv, nullptr,
        CCH, CCH, CCH, NPAD, HN, 0, sNC, sQKV, 0, 0);

    // 2) inverse norms
    finalize_inv<<<(BATCH*2*CCH + 255)/256, 256>>>();

    // 3) logits partials: split-K=7, each part K=448 (NT, fp32 partials)
    bgemm<KSPL, true, false, false, false, false, false>
        <<<dim3(CCH/128, CCH/128, BATCH*KSPL), 256>>>(
        qkvb, qkvb + (size_t)CCH*NPAD, attn, nullptr, nullptr,
        KCH, NPAD, NPAD, CCH, CCH, sQKV, sQKV, sATT, 0, (long)PSTR);

    // 4) softmax (sums partials, applies t*invq*invk) -> bf16
    softmax_rows<<<dim3(CCH, BATCH), 128>>>(temp);

    // 5) fused = attn . v (NN), bf16
    bgemm<1, false, false, false, true, false, false>
        <<<dim3(NPAD/128, CCH/128, BATCH), 256>>>(
        attnb, qkvb + (size_t)2*CCH*NPAD, fb, nullptr, nullptr,
        CCH, CCH, NPAD, NPAD, NPAD, sATT, sQKV, sFB, 0, 0);

    // 6) out = wproj . fused + b_proj + x (NN, fp32, guarded)
    bgemm<1, false, true, true, false, true, false>
        <<<dim3(NPAD/128, CCH/128, BATCH), 256>>>(
        wprojb, fb, out, b_proj, x,
        CCH, CCH, NPAD, HN, HN, 0, sFB, sOUT, sOUT, 0);
}

// round 10
// speedup vs baseline: 1.5479x; 1.0456x over previous
#include <cuda_runtime.h>
#include <cuda_bf16.h>
#include <math.h>

#define BATCH 16
#define CCH   384
#define HN    3136
#define NPAD  3200          // HN padded to multiple of 128
#define TC    1152
#define KSPL  2             // split-K factor for logits GEMM (3136 = 2*1568)
#define KCH   1568          // K per split part
#define PSTR  ((size_t)BATCH * CCH * CCH)   // partial-buffer stride

// ---------------- scratch (device globals, zero-initialized) ----------------
__device__ __nv_bfloat16 g_xT   [(size_t)BATCH * NPAD * CCH];  // BN(x)^T [b][n][c]
__device__ __nv_bfloat16 g_qkvb [(size_t)BATCH * TC * NPAD];   // qkv bf16 [b][3c][n] ld=NPAD
__device__ float         g_attn [KSPL * PSTR];                 // logits partials fp32
__device__ __nv_bfloat16 g_attnb[(size_t)BATCH * CCH * CCH];   // softmax bf16
__device__ __nv_bfloat16 g_fb   [(size_t)BATCH * CCH * NPAD];  // fused bf16 [c][n]
__device__ __nv_bfloat16 g_wqkv [TC * CCH];
__device__ __nv_bfloat16 g_wproj[CCH * CCH];
__device__ float g_sumsq[BATCH * 2 * CCH];                     // per-row sum of squares (q,k)

// ---------------- helpers ----------------
__device__ __forceinline__ unsigned su32(const void* p) {
    return (unsigned)__cvta_generic_to_shared(p);
}
__device__ __forceinline__ unsigned pk(float a, float b) {
    __nv_bfloat162 h = __floats2bfloat162_rn(a, b);
    return *(unsigned*)&h;
}
__device__ __forceinline__ void mma_bf16(float* d, const unsigned* a, unsigned b0, unsigned b1) {
    asm volatile(
        "mma.sync.aligned.m16n8k16.row.col.f32.bf16.bf16.f32 "
        "{%0,%1,%2,%3}, {%4,%5,%6,%7}, {%8,%9}, {%0,%1,%2,%3};\n"
        : "+f"(d[0]), "+f"(d[1]), "+f"(d[2]), "+f"(d[3])
        : "r"(a[0]), "r"(a[1]), "r"(a[2]), "r"(a[3]), "r"(b0), "r"(b1));
}
#define LDSM4(r0,r1,r2,r3,addr) \
    asm volatile("ldmatrix.sync.aligned.m8n8.x4.shared.b16 {%0,%1,%2,%3}, [%4];" \
        : "=r"(r0),"=r"(r1),"=r"(r2),"=r"(r3) : "r"(addr))
#define LDSM4T(r0,r1,r2,r3,addr) \
    asm volatile("ldmatrix.sync.aligned.m8n8.x4.trans.shared.b16 {%0,%1,%2,%3}, [%4];" \
        : "=r"(r0),"=r"(r1),"=r"(r2),"=r"(r3) : "r"(addr))
#define CP16(dst, src) \
    asm volatile("cp.async.cg.shared.global [%0], [%1], 16;" :: "r"(dst), "l"(src))
#define CP_COMMIT() asm volatile("cp.async.commit_group;" ::: "memory")
#define CP_WAIT1()  asm volatile("cp.async.wait_group 1;" ::: "memory")

#define STAGE_BYTES 16384   // A 8KB + B 8KB

// ============================================================
// bf16 GEMM (mma.sync), block 128x128xK32, 3-stage cp.async ring,
// 256 thr = 8 warps (4M x 2N), warp tile 32x64.
// KSP>1: blockIdx.z = zb*KSP + part; A,B advance part*K along k;
//        C goes to partial buffer at part*sPart.
// TRB=true : D[m,n] = sum_k A[m,k]*B[n,k]   (B K-major)
// TRB=false: D[m,n] = sum_k A[m,k]*B[k,n]   (B row-major, ldmatrix.trans)
// SQ: accumulate per-row sum(D^2) (cols < nvalid) into g_sumsq (rows < 768).
// ============================================================
template<int KSP, bool TRB, bool BIAS, bool RES, bool OUTBF, bool GUARDN, bool SQ>
__global__ __launch_bounds__(256, 2)
void bgemm(const __nv_bfloat16* __restrict__ A, const __nv_bfloat16* __restrict__ B,
           void* __restrict__ Cv, const float* __restrict__ bias,
           const float* __restrict__ res,
           int K, int lda, int ldb, int ldc, int nvalid,
           long sA, long sB, long sC, long sR, long sPart)
{
    __shared__ __align__(16) unsigned char smem[3 * STAGE_BYTES];
    const unsigned sbase = su32(smem);

    const int tid = threadIdx.x;
    const int wid = tid >> 5, lane = tid & 31;
    const int wm = wid >> 1, wn = wid & 1;
    const int grp = lane >> 2, qd = lane & 3;
    const int row0 = blockIdx.y * 128;
    const int col0 = blockIdx.x * 128;
    int z = blockIdx.z;
    int part = 0;
    if (KSP > 1) { part = z % KSP; z /= KSP; }

    const __nv_bfloat16* Az = A + (size_t)z * sA + (size_t)part * K;
    const __nv_bfloat16* Bz = B + (size_t)z * sB + (size_t)part * K;
    const __nv_bfloat16* Ab = Az + (size_t)row0 * lda;
    const __nv_bfloat16* Bb = TRB ? (Bz + (size_t)col0 * ldb) : (Bz + col0);

    // ---- A loader geometry (rows of 64B, 4 chunks) ----
    const int lr = tid >> 2, lc = tid & 3;
    const unsigned aoff1 = (unsigned)(lr * 64 + ((lc ^ ((lr >> 1) & 3)) * 16));
    const int lr2 = lr + 64;
    const unsigned aoff2 = (unsigned)(lr2 * 64 + ((lc ^ ((lr2 >> 1) & 3)) * 16));

    // ---- NN B loader geometry (32 k-rows x 16 chunks -> 2 halves) ----
    const int nk1 = tid >> 4, nc1 = tid & 15;
    const unsigned nboff1 = (unsigned)((nc1 >> 3) * 4096 + nk1 * 128 + (((nc1 & 7) ^ (nk1 & 7)) * 16));
    const int nk2 = (tid + 256) >> 4, nc2 = tid & 15;
    const unsigned nboff2 = (unsigned)((nc2 >> 3) * 4096 + nk2 * 128 + (((nc2 & 7) ^ (nk2 & 7)) * 16));

    const int T = K >> 5;

    // ---- fragment geometry ----
    int arow_l[2];
    #pragma unroll
    for (int mi = 0; mi < 2; mi++) arow_l[mi] = wm * 32 + mi * 16 + (lane & 15);
    const int achk = lane >> 4;
    const int bn_base = wn * 64 + ((lane >> 4) << 3) + (lane & 7);
    const int boct = (lane >> 3) & 1;
    const int nn_kl = lane & 15;
    const int nn_ch = lane >> 4;

    float acc[2][8][4] = {};

    auto issue = [&](int s, int k0) {
        const unsigned sa = sbase + s * STAGE_BYTES;
        const unsigned sb = sa + 8192;
        CP16(sa + aoff1, Ab + (size_t)lr  * lda + k0 + lc * 8);
        CP16(sa + aoff2, Ab + (size_t)lr2 * lda + k0 + lc * 8);
        if (TRB) {
            CP16(sb + aoff1, Bb + (size_t)lr  * ldb + k0 + lc * 8);
            CP16(sb + aoff2, Bb + (size_t)lr2 * ldb + k0 + lc * 8);
        } else {
            CP16(sb + nboff1, Bb + (size_t)(k0 + nk1) * ldb + nc1 * 8);
            CP16(sb + nboff2, Bb + (size_t)(k0 + nk2) * ldb + nc2 * 8);
        }
        CP_COMMIT();
    };

    issue(0, 0);
    issue(1, 32);

    for (int t = 0; t < T; t++) {
        CP_WAIT1();
        __syncthreads();

        if (t + 2 < T) issue((t + 2) % 3, (t + 2) << 5);
        else CP_COMMIT();

        const unsigned sa = sbase + (t % 3) * STAGE_BYTES;
        const unsigned sb = sa + 8192;

        #pragma unroll
        for (int ks = 0; ks < 2; ks++) {
            unsigned af[2][4];
            #pragma unroll
            for (int mi = 0; mi < 2; mi++) {
                unsigned addr = sa + arow_l[mi] * 64 +
                    (((ks * 2 + achk) ^ ((arow_l[mi] >> 1) & 3)) * 16);
                LDSM4(af[mi][0], af[mi][1], af[mi][2], af[mi][3], addr);
            }
            unsigned bq[4][4];
            if (TRB) {
                #pragma unroll
                for (int nj = 0; nj < 4; nj++) {
                    int nl = bn_base + nj * 16;
                    unsigned addr = sb + nl * 64 +
                        (((ks * 2 + boct) ^ ((nl >> 1) & 3)) * 16);
                    LDSM4(bq[nj][0], bq[nj][1], bq[nj][2], bq[nj][3], addr);
                }
            } else {
                const int kl = ks * 16 + nn_kl;
                const unsigned sbh = sb + wn * 4096 + kl * 128;
                #pragma unroll
                for (int nj = 0; nj < 4; nj++) {
                    unsigned addr = sbh + (((nj * 2 + nn_ch) ^ (kl & 7)) * 16);
                    LDSM4T(bq[nj][0], bq[nj][1], bq[nj][2], bq[nj][3], addr);
                }
            }
            #pragma unroll
            for (int nj = 0; nj < 4; nj++) {
                #pragma unroll
                for (int p = 0; p < 2; p++) {
                    unsigned b0 = bq[nj][p * 2], b1 = bq[nj][p * 2 + 1];
                    const int ni = nj * 2 + p;
                    #pragma unroll
                    for (int mi = 0; mi < 2; mi++)
                        mma_bf16(acc[mi][ni], af[mi], b0, b1);
                }
            }
        }
    }

    // ---- epilogue ----
    const bool sq_blk = SQ && (row0 < 2 * CCH);
    #pragma unroll
    for (int mi = 0; mi < 2; mi++) {
        const int r0 = row0 + wm * 32 + mi * 16 + grp;
        const int r1 = r0 + 8;
        float bv0 = 0.0f, bv1 = 0.0f;
        if (BIAS) { bv0 = bias[r0]; bv1 = bias[r1]; }
        float s0 = 0.0f, s1 = 0.0f;
        #pragma unroll
        for (int ni = 0; ni < 8; ni++) {
            const int c = col0 + wn * 64 + ni * 8 + 2 * qd;
            if (GUARDN && c >= nvalid) continue;
            float d0 = acc[mi][ni][0] + bv0, d1 = acc[mi][ni][1] + bv0;
            float d2 = acc[mi][ni][2] + bv1, d3 = acc[mi][ni][3] + bv1;
            if (RES) {
                const float* rp = res + (size_t)z * sR;
                float2 q0 = *(const float2*)&rp[(size_t)r0 * ldc + c];
                float2 q1 = *(const float2*)&rp[(size_t)r1 * ldc + c];
                d0 += q0.x; d1 += q0.y; d2 += q1.x; d3 += q1.y;
            }
            if (SQ) {
                if (sq_blk && c < nvalid) {
                    s0 += d0 * d0 + d1 * d1;
                    s1 += d2 * d2 + d3 * d3;
                }
            }
            if (OUTBF) {
                __nv_bfloat16* Cb = (__nv_bfloat16*)Cv + (size_t)z * sC;
                *(unsigned*)&Cb[(size_t)r0 * ldc + c] = pk(d0, d1);
                *(unsigned*)&Cb[(size_t)r1 * ldc + c] = pk(d2, d3);
            } else {
                float* Cf = (float*)Cv + (size_t)z * sC + (size_t)part * sPart;
                *(float2*)&Cf[(size_t)r0 * ldc + c] = make_float2(d0, d1);
                *(float2*)&Cf[(size_t)r1 * ldc + c] = make_float2(d2, d3);
            }
        }
        if (SQ && sq_blk) {
            s0 += __shfl_xor_sync(0xffffffffu, s0, 1);
            s0 += __shfl_xor_sync(0xffffffffu, s0, 2);
            s1 += __shfl_xor_sync(0xffffffffu, s1, 1);
            s1 += __shfl_xor_sync(0xffffffffu, s1, 2);
            if (qd == 0) {
                atomicAdd(&g_sumsq[(size_t)z * 2 * CCH + r0], s0);
                atomicAdd(&g_sumsq[(size_t)z * 2 * CCH + r1], s1);
            }
        }
    }
}

// ---------------- prep / elementwise ----------------
// both weights -> bf16 in one launch
__global__ void f2b2(const float* __restrict__ s1, int n1,
                     const float* __restrict__ s2, int n2) {
    int i = blockIdx.x * 256 + threadIdx.x;
    if (i < n1) g_wqkv[i] = __float2bfloat16(s1[i]);
    else if (i < n1 + n2) g_wproj[i - n1] = __float2bfloat16(s2[i - n1]);
}

// x [b][c][3136] fp32 --BN (inline fold)--> xT [b][n][384] bf16. 64x64 tiles.
__global__ __launch_bounds__(256)
void prep_xT(const float* __restrict__ x,
             const float* __restrict__ gamma, const float* __restrict__ beta,
             const float* __restrict__ mean,  const float* __restrict__ var) {
    __shared__ float tl[64][65];
    const int b = blockIdx.z;
    const int n0 = blockIdx.x * 64, c0 = blockIdx.y * 64;
    const int tid = threadIdx.x;
    const float* xb = x + (size_t)b * CCH * HN;

    // load: 64 c-rows x 16 float4 (64 n), 4 per thread; BN fold inline
    {
        const int cl = tid >> 2;                 // 0..63
        const int c = c0 + cl;
        const float s = gamma[c] * rsqrtf(var[c] + 1e-5f);
        const float h = beta[c] - mean[c] * s;
        const float* src = xb + (size_t)c * HN + n0;
        #pragma unroll
        for (int j = 0; j < 4; j++) {
            int f = (tid & 3) + j * 4;           // 0..15
            float4 v = *(const float4*)(src + f * 4);
            tl[cl][f * 4 + 0] = v.x * s + h;
            tl[cl][f * 4 + 1] = v.y * s + h;
            tl[cl][f * 4 + 2] = v.z * s + h;
            tl[cl][f * 4 + 3] = v.w * s + h;
        }
    }
    __syncthreads();

    // store: 64 n-rows x 8 uint4 (64 c as bf16), 2 per thread
    {
        const int nl = tid >> 2;                 // 0..63
        __nv_bfloat16* dst = g_xT + (size_t)b * NPAD * CCH + (size_t)(n0 + nl) * CCH + c0;
        #pragma unroll
        for (int j = 0; j < 2; j++) {
            int u = (tid & 3) + j * 4;           // 0..7
            int cc = u * 8;
            uint4 o;
            o.x = pk(tl[cc + 0][nl], tl[cc + 1][nl]);
            o.y = pk(tl[cc + 2][nl], tl[cc + 3][nl]);
            o.z = pk(tl[cc + 4][nl], tl[cc + 5][nl]);
            o.w = pk(tl[cc + 6][nl], tl[cc + 7][nl]);
            *(uint4*)(dst + cc) = o;
        }
    }
}

// softmax over last dim (384): sums KSPL partials, applies t*invq[c]*invk[d]
// (inverse norms computed inline from g_sumsq)
__global__ __launch_bounds__(128)
void softmax_rows(const float* __restrict__ tptr) {
    const int b = blockIdx.y, cc = blockIdx.x;
    const size_t ridx = (size_t)b * CCH + cc;
    const float* row = g_attn + ridx * CCH;
    __nv_bfloat16* orow = g_attnb + ridx * CCH;
    const int tid = threadIdx.x;
    __shared__ float red[128];

    const float* ssq = g_sumsq + (size_t)b * 2 * CCH;
    const float tq = tptr[0] / fmaxf(sqrtf(ssq[cc]), 1e-12f);
    const float* sk = ssq + CCH;
    const float ik0 = 1.0f / fmaxf(sqrtf(sk[tid]),       1e-12f);
    const float ik1 = 1.0f / fmaxf(sqrtf(sk[tid + 128]), 1e-12f);
    const float ik2 = 1.0f / fmaxf(sqrtf(sk[tid + 256]), 1e-12f);

    float v0 = 0.0f, v1 = 0.0f, v2 = 0.0f;
    #pragma unroll
    for (int p = 0; p < KSPL; p++) {
        const float* rp = row + (size_t)p * PSTR;
        v0 += rp[tid];
        v1 += rp[tid + 128];
        v2 += rp[tid + 256];
    }
    v0 *= tq * ik0;
    v1 *= tq * ik1;
    v2 *= tq * ik2;

    float m = fmaxf(v0, fmaxf(v1, v2));
    red[tid] = m;
    __syncthreads();
    for (int s = 64; s > 0; s >>= 1) {
        if (tid < s) red[tid] = fmaxf(red[tid], red[tid + s]);
        __syncthreads();
    }
    m = red[0];
    __syncthreads();

    float e0 = expf(v0 - m), e1 = expf(v1 - m), e2 = expf(v2 - m);
    red[tid] = e0 + e1 + e2;
    __syncthreads();
    for (int s = 64; s > 0; s >>= 1) {
        if (tid < s) red[tid] += red[tid + s];
        __syncthreads();
    }
    float inv = 1.0f / red[0];

    orow[tid]       = __float2bfloat16(e0 * inv);
    orow[tid + 128] = __float2bfloat16(e1 * inv);
    orow[tid + 256] = __float2bfloat16(e2 * inv);
}

// ---------------- host ----------------
extern "C" void kernel_launch(void* const* d_in, const int* in_sizes, int n_in,
                              void* d_out, int out_size)
{
    const float* x      = (const float*)d_in[0];
    const float* w_qkv  = (const float*)d_in[1];
    const float* b_qkv  = (const float*)d_in[2];
    const float* w_proj = (const float*)d_in[3];
    const float* b_proj = (const float*)d_in[4];
    const float* gamma  = (const float*)d_in[5];
    const float* beta   = (const float*)d_in[6];
    const float* mean   = (const float*)d_in[7];
    const float* var    = (const float*)d_in[8];
    const float* temp   = (const float*)d_in[9];
    float* out = (float*)d_out;

    __nv_bfloat16 *qkvb, *attnb, *fb, *wqkvb, *wprojb, *xT;
    float *attn, *sumsq;
    cudaGetSymbolAddress((void**)&xT,     g_xT);
    cudaGetSymbolAddress((void**)&qkvb,   g_qkvb);
    cudaGetSymbolAddress((void**)&attn,   g_attn);
    cudaGetSymbolAddress((void**)&attnb,  g_attnb);
    cudaGetSymbolAddress((void**)&fb,     g_fb);
    cudaGetSymbolAddress((void**)&wqkvb,  g_wqkv);
    cudaGetSymbolAddress((void**)&wprojb, g_wproj);
    cudaGetSymbolAddress((void**)&sumsq,  g_sumsq);

    const long sQKV = (long)TC * NPAD;
    const long sNC  = (long)NPAD * CCH;
    const long sATT = (long)CCH * CCH;
    const long sFB  = (long)CCH * NPAD;
    const long sOUT = (long)CCH * HN;

    // 0) prep
    cudaMemsetAsync(sumsq, 0, (size_t)BATCH * 2 * CCH * sizeof(float));
    f2b2<<<(TC*CCH + CCH*CCH + 255)/256, 256>>>(w_qkv, TC*CCH, w_proj, CCH*CCH);
    prep_xT<<<dim3(HN/64, CCH/64, BATCH), 256>>>(x, gamma, beta, mean, var);

    // 1) qkv = wqkv . xT^T + b_qkv (NT) + fused q/k sum-of-squares
    bgemm<1, true, true, false, true, false, true>
        <<<dim3(NPAD/128, TC/128, BATCH), 256>>>(
        wqkvb, xT, qkvb, b_qkv, nullptr,
        CCH, CCH, CCH, NPAD, HN, 0, sNC, sQKV, 0, 0);

    // 2) logits partials: split-K=2, each part K=1568 (NT, fp32 partials)
    bgemm<KSPL, true, false, false, false, false, false>
        <<<dim3(CCH/128, CCH/128, BATCH*KSPL), 256>>>(
        qkvb, qkvb + (size_t)CCH*NPAD, attn, nullptr, nullptr,
        KCH, NPAD, NPAD, CCH, CCH, sQKV, sQKV, sATT, 0, (long)PSTR);

    // 3) softmax (sums partials, inline inverse norms, temperature) -> bf16
    softmax_rows<<<dim3(CCH, BATCH), 128>>>(temp);

    // 4) fused = attn . v (NN), bf16
    bgemm<1, false, false, false, true, false, false>
        <<<dim3(NPAD/128, CCH/128, BATCH), 256>>>(
        attnb, qkvb + (size_t)2*CCH*NPAD, fb, nullptr, nullptr,
        CCH, CCH, NPAD, NPAD, NPAD, sATT, sQKV, sFB, 0, 0);

    // 5) out = wproj . fused + b_proj + x (NN, fp32, guarded)
    bgemm<1, false, true, true, false, true, false>
        <<<dim3(NPAD/128, CCH/128, BATCH), 256>>>(
        wprojb, fb, out, b_proj, x,
        CCH, CCH, NPAD, HN, HN, 0, sFB, sOUT, sOUT, 0);
}

// round 11
// speedup vs baseline: 1.7502x; 1.1307x over previous
#include <cuda_runtime.h>
#include <cuda_bf16.h>
#include <math.h>

#define BATCH 16
#define CCH   384
#define HN    3136
#define NPAD  3200          // HN padded to multiple of 128
#define TC    1152
#define KSPL  2             // split-K factor for logits GEMM (3136 = 2*1568)
#define KCH   1568          // K per split part
#define PSTR  ((size_t)BATCH * CCH * CCH)   // partial-buffer stride

// ---------------- scratch (device globals, zero-initialized) ----------------
__device__ __nv_bfloat16 g_xT   [(size_t)BATCH * NPAD * CCH];  // BN(x)^T [b][n][c]
__device__ __nv_bfloat16 g_qkvb [(size_t)BATCH * TC * NPAD];   // qkv bf16 [b][3c][n] ld=NPAD
__device__ float         g_attn [KSPL * PSTR];                 // logits partials fp32
__device__ __nv_bfloat16 g_attnb[(size_t)BATCH * CCH * CCH];   // softmax bf16 [c][d]
__device__ __nv_bfloat16 g_w2   [(size_t)BATCH * CCH * CCH];   // W2 = wproj@attn, bf16 [o][d]
__device__ __nv_bfloat16 g_wqkv [TC * CCH];
__device__ __nv_bfloat16 g_wproj[CCH * CCH];
__device__ float g_sumsq[BATCH * 2 * CCH];                     // per-row sum of squares (q,k)

// ---------------- helpers ----------------
__device__ __forceinline__ unsigned su32(const void* p) {
    return (unsigned)__cvta_generic_to_shared(p);
}
__device__ __forceinline__ unsigned pk(float a, float b) {
    __nv_bfloat162 h = __floats2bfloat162_rn(a, b);
    return *(unsigned*)&h;
}
__device__ __forceinline__ void mma_bf16(float* d, const unsigned* a, unsigned b0, unsigned b1) {
    asm volatile(
        "mma.sync.aligned.m16n8k16.row.col.f32.bf16.bf16.f32 "
        "{%0,%1,%2,%3}, {%4,%5,%6,%7}, {%8,%9}, {%0,%1,%2,%3};\n"
        : "+f"(d[0]), "+f"(d[1]), "+f"(d[2]), "+f"(d[3])
        : "r"(a[0]), "r"(a[1]), "r"(a[2]), "r"(a[3]), "r"(b0), "r"(b1));
}
#define LDSM4(r0,r1,r2,r3,addr) \
    asm volatile("ldmatrix.sync.aligned.m8n8.x4.shared.b16 {%0,%1,%2,%3}, [%4];" \
        : "=r"(r0),"=r"(r1),"=r"(r2),"=r"(r3) : "r"(addr))
#define LDSM4T(r0,r1,r2,r3,addr) \
    asm volatile("ldmatrix.sync.aligned.m8n8.x4.trans.shared.b16 {%0,%1,%2,%3}, [%4];" \
        : "=r"(r0),"=r"(r1),"=r"(r2),"=r"(r3) : "r"(addr))
#define CP16(dst, src) \
    asm volatile("cp.async.cg.shared.global [%0], [%1], 16;" :: "r"(dst), "l"(src))
#define CP_COMMIT() asm volatile("cp.async.commit_group;" ::: "memory")
#define CP_WAIT1()  asm volatile("cp.async.wait_group 1;" ::: "memory")

#define STAGE_BYTES 16384   // A 8KB + B 8KB

// ============================================================
// bf16 GEMM (mma.sync), block 128x128xK32, 3-stage cp.async ring,
// 256 thr = 8 warps (4M x 2N), warp tile 32x64.
// KSP>1: blockIdx.z = zb*KSP + part; A,B advance part*K along k;
//        C goes to partial buffer at part*sPart.
// TRB=true : D[m,n] = sum_k A[m,k]*B[n,k]   (B K-major)
// TRB=false: D[m,n] = sum_k A[m,k]*B[k,n]   (B row-major, ldmatrix.trans)
// SQ: accumulate per-row sum(D^2) (cols < nvalid) into g_sumsq (rows < 768).
// ============================================================
template<int KSP, bool TRB, bool BIAS, bool RES, bool OUTBF, bool GUARDN, bool SQ>
__global__ __launch_bounds__(256, 2)
void bgemm(const __nv_bfloat16* __restrict__ A, const __nv_bfloat16* __restrict__ B,
           void* __restrict__ Cv, const float* __restrict__ bias,
           const float* __restrict__ res,
           int K, int lda, int ldb, int ldc, int nvalid,
           long sA, long sB, long sC, long sR, long sPart)
{
    __shared__ __align__(16) unsigned char smem[3 * STAGE_BYTES];
    const unsigned sbase = su32(smem);

    const int tid = threadIdx.x;
    const int wid = tid >> 5, lane = tid & 31;
    const int wm = wid >> 1, wn = wid & 1;
    const int grp = lane >> 2, qd = lane & 3;
    const int row0 = blockIdx.y * 128;
    const int col0 = blockIdx.x * 128;
    int z = blockIdx.z;
    int part = 0;
    if (KSP > 1) { part = z % KSP; z /= KSP; }

    const __nv_bfloat16* Az = A + (size_t)z * sA + (size_t)part * K;
    const __nv_bfloat16* Bz = B + (size_t)z * sB + (size_t)part * K;
    const __nv_bfloat16* Ab = Az + (size_t)row0 * lda;
    const __nv_bfloat16* Bb = TRB ? (Bz + (size_t)col0 * ldb) : (Bz + col0);

    // ---- A loader geometry (rows of 64B, 4 chunks) ----
    const int lr = tid >> 2, lc = tid & 3;
    const unsigned aoff1 = (unsigned)(lr * 64 + ((lc ^ ((lr >> 1) & 3)) * 16));
    const int lr2 = lr + 64;
    const unsigned aoff2 = (unsigned)(lr2 * 64 + ((lc ^ ((lr2 >> 1) & 3)) * 16));

    // ---- NN B loader geometry (32 k-rows x 16 chunks -> 2 halves) ----
    const int nk1 = tid >> 4, nc1 = tid & 15;
    const unsigned nboff1 = (unsigned)((nc1 >> 3) * 4096 + nk1 * 128 + (((nc1 & 7) ^ (nk1 & 7)) * 16));
    const int nk2 = (tid + 256) >> 4, nc2 = tid & 15;
    const unsigned nboff2 = (unsigned)((nc2 >> 3) * 4096 + nk2 * 128 + (((nc2 & 7) ^ (nk2 & 7)) * 16));

    const int T = K >> 5;

    // ---- fragment geometry ----
    int arow_l[2];
    #pragma unroll
    for (int mi = 0; mi < 2; mi++) arow_l[mi] = wm * 32 + mi * 16 + (lane & 15);
    const int achk = lane >> 4;
    const int bn_base = wn * 64 + ((lane >> 4) << 3) + (lane & 7);
    const int boct = (lane >> 3) & 1;
    const int nn_kl = lane & 15;
    const int nn_ch = lane >> 4;

    float acc[2][8][4] = {};

    auto issue = [&](int s, int k0) {
        const unsigned sa = sbase + s * STAGE_BYTES;
        const unsigned sb = sa + 8192;
        CP16(sa + aoff1, Ab + (size_t)lr  * lda + k0 + lc * 8);
        CP16(sa + aoff2, Ab + (size_t)lr2 * lda + k0 + lc * 8);
        if (TRB) {
            CP16(sb + aoff1, Bb + (size_t)lr  * ldb + k0 + lc * 8);
            CP16(sb + aoff2, Bb + (size_t)lr2 * ldb + k0 + lc * 8);
        } else {
            CP16(sb + nboff1, Bb + (size_t)(k0 + nk1) * ldb + nc1 * 8);
            CP16(sb + nboff2, Bb + (size_t)(k0 + nk2) * ldb + nc2 * 8);
        }
        CP_COMMIT();
    };

    issue(0, 0);
    issue(1, 32);

    for (int t = 0; t < T; t++) {
        CP_WAIT1();
        __syncthreads();

        if (t + 2 < T) issue((t + 2) % 3, (t + 2) << 5);
        else CP_COMMIT();

        const unsigned sa = sbase + (t % 3) * STAGE_BYTES;
        const unsigned sb = sa + 8192;

        #pragma unroll
        for (int ks = 0; ks < 2; ks++) {
            unsigned af[2][4];
            #pragma unroll
            for (int mi = 0; mi < 2; mi++) {
                unsigned addr = sa + arow_l[mi] * 64 +
                    (((ks * 2 + achk) ^ ((arow_l[mi] >> 1) & 3)) * 16);
                LDSM4(af[mi][0], af[mi][1], af[mi][2], af[mi][3], addr);
            }
            unsigned bq[4][4];
            if (TRB) {
                #pragma unroll
                for (int nj = 0; nj < 4; nj++) {
                    int nl = bn_base + nj * 16;
                    unsigned addr = sb + nl * 64 +
                        (((ks * 2 + boct) ^ ((nl >> 1) & 3)) * 16);
                    LDSM4(bq[nj][0], bq[nj][1], bq[nj][2], bq[nj][3], addr);
                }
            } else {
                const int kl = ks * 16 + nn_kl;
                const unsigned sbh = sb + wn * 4096 + kl * 128;
                #pragma unroll
                for (int nj = 0; nj < 4; nj++) {
                    unsigned addr = sbh + (((nj * 2 + nn_ch) ^ (kl & 7)) * 16);
                    LDSM4T(bq[nj][0], bq[nj][1], bq[nj][2], bq[nj][3], addr);
                }
            }
            #pragma unroll
            for (int nj = 0; nj < 4; nj++) {
                #pragma unroll
                for (int p = 0; p < 2; p++) {
                    unsigned b0 = bq[nj][p * 2], b1 = bq[nj][p * 2 + 1];
                    const int ni = nj * 2 + p;
                    #pragma unroll
                    for (int mi = 0; mi < 2; mi++)
                        mma_bf16(acc[mi][ni], af[mi], b0, b1);
                }
            }
        }
    }

    // ---- epilogue ----
    const bool sq_blk = SQ && (row0 < 2 * CCH);
    #pragma unroll
    for (int mi = 0; mi < 2; mi++) {
        const int r0 = row0 + wm * 32 + mi * 16 + grp;
        const int r1 = r0 + 8;
        float bv0 = 0.0f, bv1 = 0.0f;
        if (BIAS) { bv0 = bias[r0]; bv1 = bias[r1]; }
        float s0 = 0.0f, s1 = 0.0f;
        #pragma unroll
        for (int ni = 0; ni < 8; ni++) {
            const int c = col0 + wn * 64 + ni * 8 + 2 * qd;
            if (GUARDN && c >= nvalid) continue;
            float d0 = acc[mi][ni][0] + bv0, d1 = acc[mi][ni][1] + bv0;
            float d2 = acc[mi][ni][2] + bv1, d3 = acc[mi][ni][3] + bv1;
            if (RES) {
                const float* rp = res + (size_t)z * sR;
                float2 q0 = *(const float2*)&rp[(size_t)r0 * ldc + c];
                float2 q1 = *(const float2*)&rp[(size_t)r1 * ldc + c];
                d0 += q0.x; d1 += q0.y; d2 += q1.x; d3 += q1.y;
            }
            if (SQ) {
                if (sq_blk && c < nvalid) {
                    s0 += d0 * d0 + d1 * d1;
                    s1 += d2 * d2 + d3 * d3;
                }
            }
            if (OUTBF) {
                __nv_bfloat16* Cb = (__nv_bfloat16*)Cv + (size_t)z * sC;
                *(unsigned*)&Cb[(size_t)r0 * ldc + c] = pk(d0, d1);
                *(unsigned*)&Cb[(size_t)r1 * ldc + c] = pk(d2, d3);
            } else {
                float* Cf = (float*)Cv + (size_t)z * sC + (size_t)part * sPart;
                *(float2*)&Cf[(size_t)r0 * ldc + c] = make_float2(d0, d1);
                *(float2*)&Cf[(size_t)r1 * ldc + c] = make_float2(d2, d3);
            }
        }
        if (SQ && sq_blk) {
            s0 += __shfl_xor_sync(0xffffffffu, s0, 1);
            s0 += __shfl_xor_sync(0xffffffffu, s0, 2);
            s1 += __shfl_xor_sync(0xffffffffu, s1, 1);
            s1 += __shfl_xor_sync(0xffffffffu, s1, 2);
            if (qd == 0) {
                atomicAdd(&g_sumsq[(size_t)z * 2 * CCH + r0], s0);
                atomicAdd(&g_sumsq[(size_t)z * 2 * CCH + r1], s1);
            }
        }
    }
}

// ---------------- prep / elementwise ----------------
// both weights -> bf16 in one launch
__global__ void f2b2(const float* __restrict__ s1, int n1,
                     const float* __restrict__ s2, int n2) {
    int i = blockIdx.x * 256 + threadIdx.x;
    if (i < n1) g_wqkv[i] = __float2bfloat16(s1[i]);
    else if (i < n1 + n2) g_wproj[i - n1] = __float2bfloat16(s2[i - n1]);
}

// x [b][c][3136] fp32 --BN (inline fold)--> xT [b][n][384] bf16. 64x64 tiles.
__global__ __launch_bounds__(256)
void prep_xT(const float* __restrict__ x,
             const float* __restrict__ gamma, const float* __restrict__ beta,
             const float* __restrict__ mean,  const float* __restrict__ var) {
    __shared__ float tl[64][65];
    const int b = blockIdx.z;
    const int n0 = blockIdx.x * 64, c0 = blockIdx.y * 64;
    const int tid = threadIdx.x;
    const float* xb = x + (size_t)b * CCH * HN;

    {
        const int cl = tid >> 2;                 // 0..63
        const int c = c0 + cl;
        const float s = gamma[c] * rsqrtf(var[c] + 1e-5f);
        const float h = beta[c] - mean[c] * s;
        const float* src = xb + (size_t)c * HN + n0;
        #pragma unroll
        for (int j = 0; j < 4; j++) {
            int f = (tid & 3) + j * 4;           // 0..15
            float4 v = *(const float4*)(src + f * 4);
            tl[cl][f * 4 + 0] = v.x * s + h;
            tl[cl][f * 4 + 1] = v.y * s + h;
            tl[cl][f * 4 + 2] = v.z * s + h;
            tl[cl][f * 4 + 3] = v.w * s + h;
        }
    }
    __syncthreads();

    {
        const int nl = tid >> 2;                 // 0..63
        __nv_bfloat16* dst = g_xT + (size_t)b * NPAD * CCH + (size_t)(n0 + nl) * CCH + c0;
        #pragma unroll
        for (int j = 0; j < 2; j++) {
            int u = (tid & 3) + j * 4;           // 0..7
            int cc = u * 8;
            uint4 o;
            o.x = pk(tl[cc + 0][nl], tl[cc + 1][nl]);
            o.y = pk(tl[cc + 2][nl], tl[cc + 3][nl]);
            o.z = pk(tl[cc + 4][nl], tl[cc + 5][nl]);
            o.w = pk(tl[cc + 6][nl], tl[cc + 7][nl]);
            *(uint4*)(dst + cc) = o;
        }
    }
}

// softmax over last dim (384): sums KSPL partials, applies t*invq[c]*invk[d]
__global__ __launch_bounds__(128)
void softmax_rows(const float* __restrict__ tptr) {
    const int b = blockIdx.y, cc = blockIdx.x;
    const size_t ridx = (size_t)b * CCH + cc;
    const float* row = g_attn + ridx * CCH;
    __nv_bfloat16* orow = g_attnb + ridx * CCH;
    const int tid = threadIdx.x;
    __shared__ float red[128];

    const float* ssq = g_sumsq + (size_t)b * 2 * CCH;
    const float tq = tptr[0] / fmaxf(sqrtf(ssq[cc]), 1e-12f);
    const float* sk = ssq + CCH;
    const float ik0 = 1.0f / fmaxf(sqrtf(sk[tid]),       1e-12f);
    const float ik1 = 1.0f / fmaxf(sqrtf(sk[tid + 128]), 1e-12f);
    const float ik2 = 1.0f / fmaxf(sqrtf(sk[tid + 256]), 1e-12f);

    float v0 = 0.0f, v1 = 0.0f, v2 = 0.0f;
    #pragma unroll
    for (int p = 0; p < KSPL; p++) {
        const float* rp = row + (size_t)p * PSTR;
        v0 += rp[tid];
        v1 += rp[tid + 128];
        v2 += rp[tid + 256];
    }
    v0 *= tq * ik0;
    v1 *= tq * ik1;
    v2 *= tq * ik2;

    float m = fmaxf(v0, fmaxf(v1, v2));
    red[tid] = m;
    __syncthreads();
    for (int s = 64; s > 0; s >>= 1) {
        if (tid < s) red[tid] = fmaxf(red[tid], red[tid + s]);
        __syncthreads();
    }
    m = red[0];
    __syncthreads();

    float e0 = expf(v0 - m), e1 = expf(v1 - m), e2 = expf(v2 - m);
    red[tid] = e0 + e1 + e2;
    __syncthreads();
    for (int s = 64; s > 0; s >>= 1) {
        if (tid < s) red[tid] += red[tid + s];
        __syncthreads();
    }
    float inv = 1.0f / red[0];

    orow[tid]       = __float2bfloat16(e0 * inv);
    orow[tid + 128] = __float2bfloat16(e1 * inv);
    orow[tid + 256] = __float2bfloat16(e2 * inv);
}

// ---------------- host ----------------
extern "C" void kernel_launch(void* const* d_in, const int* in_sizes, int n_in,
                              void* d_out, int out_size)
{
    const float* x      = (const float*)d_in[0];
    const float* w_qkv  = (const float*)d_in[1];
    const float* b_qkv  = (const float*)d_in[2];
    const float* w_proj = (const float*)d_in[3];
    const float* b_proj = (const float*)d_in[4];
    const float* gamma  = (const float*)d_in[5];
    const float* beta   = (const float*)d_in[6];
    const float* mean   = (const float*)d_in[7];
    const float* var    = (const float*)d_in[8];
    const float* temp   = (const float*)d_in[9];
    float* out = (float*)d_out;

    __nv_bfloat16 *qkvb, *attnb, *w2, *wqkvb, *wprojb, *xT;
    float *attn, *sumsq;
    cudaGetSymbolAddress((void**)&xT,     g_xT);
    cudaGetSymbolAddress((void**)&qkvb,   g_qkvb);
    cudaGetSymbolAddress((void**)&attn,   g_attn);
    cudaGetSymbolAddress((void**)&attnb,  g_attnb);
    cudaGetSymbolAddress((void**)&w2,     g_w2);
    cudaGetSymbolAddress((void**)&wqkvb,  g_wqkv);
    cudaGetSymbolAddress((void**)&wprojb, g_wproj);
    cudaGetSymbolAddress((void**)&sumsq,  g_sumsq);

    const long sQKV = (long)TC * NPAD;
    const long sNC  = (long)NPAD * CCH;
    const long sATT = (long)CCH * CCH;
    const long sOUT = (long)CCH * HN;

    // 0) prep
    cudaMemsetAsync(sumsq, 0, (size_t)BATCH * 2 * CCH * sizeof(float));
    f2b2<<<(TC*CCH + CCH*CCH + 255)/256, 256>>>(w_qkv, TC*CCH, w_proj, CCH*CCH);
    prep_xT<<<dim3(HN/64, CCH/64, BATCH), 256>>>(x, gamma, beta, mean, var);

    // 1) qkv = wqkv . xT^T + b_qkv (NT) + fused q/k sum-of-squares
    bgemm<1, true, true, false, true, false, true>
        <<<dim3(NPAD/128, TC/128, BATCH), 256>>>(
        wqkvb, xT, qkvb, b_qkv, nullptr,
        CCH, CCH, CCH, NPAD, HN, 0, sNC, sQKV, 0, 0);

    // 2) logits partials: split-K=2, each part K=1568 (NT, fp32 partials)
    bgemm<KSPL, true, false, false, false, false, false>
        <<<dim3(CCH/128, CCH/128, BATCH*KSPL), 256>>>(
        qkvb, qkvb + (size_t)CCH*NPAD, attn, nullptr, nullptr,
        KCH, NPAD, NPAD, CCH, CCH, sQKV, sQKV, sATT, 0, (long)PSTR);

    // 3) softmax (sums partials, inline inverse norms, temperature) -> bf16
    softmax_rows<<<dim3(CCH, BATCH), 128>>>(temp);

    // 4) W2[o,d] = wproj[o,:] . attn[:,d]   (NN small GEMM, 384x384x384), bf16
    bgemm<1, false, false, false, true, false, false>
        <<<dim3(CCH/128, CCH/128, BATCH), 256>>>(
        wprojb, attnb, w2, nullptr, nullptr,
        CCH, CCH, CCH, CCH, CCH, 0, sATT, sATT, 0, 0);

    // 5) out[o,n] = W2[o,:] . v[:,n] + b_proj + x   (NN, fp32, guarded)
    bgemm<1, false, true, true, false, true, false>
        <<<dim3(NPAD/128, CCH/128, BATCH), 256>>>(
        w2, qkvb + (size_t)2*CCH*NPAD, out, b_proj, x,
        CCH, CCH, NPAD, HN, HN, sATT, sQKV, sOUT, sOUT, 0);
}